// round 1
// baseline (speedup 1.0000x reference)
#include <cuda_runtime.h>
#include <cuda_bf16.h>
#include <math.h>

#define NN 100000
#define EE 1600000
#define HID 128
#define NEG 0.01f
#define BN_EPS 1e-5f
#define L2_EPS 1e-12f
#define NSTAT 512   // blocks for column stats

// ------------------------- device scratch -------------------------
__device__ float g_Tcat[(size_t)NN * 512];   // [Tx0|Tx1|Tx2|Tx3] concatenated per row
__device__ float g_H[(size_t)NN * 128];      // GEMM output (pre-activation)
__device__ float g_t1[NN * 3];
__device__ float g_t2[NN * 3];
__device__ float g_t3[NN * 3];
__device__ float g_deg[NN];
__device__ float g_dinv[NN];
__device__ int   g_indeg[NN];
__device__ int   g_ptr[NN + 1];
__device__ int   g_fill[NN];
__device__ int   g_bsums[256];
__device__ int   g_src[EE];
__device__ float g_w[EE];
__device__ float g_part[NSTAT * 256];
__device__ float g_scale[128];
__device__ float g_shift[128];
__device__ int   g_is64;

// ------------------------- helpers -------------------------
__device__ __forceinline__ void load_edge(const void* ei, int E, int e, int& s, int& d) {
    if (g_is64) {
        const long long* p = (const long long*)ei;
        s = (int)p[e];
        d = (int)p[(size_t)E + e];
    } else {
        const int* p = (const int*)ei;
        s = p[e];
        d = p[E + e];
    }
}

// ------------------------- setup kernels -------------------------
__global__ void k_detect(const int* ei32) {
    if (threadIdx.x == 0 && blockIdx.x == 0) {
        int is64 = 1;
        for (int i = 0; i < 32; i++) {
            if (ei32[2 * i + 1] != 0) { is64 = 0; break; }
        }
        g_is64 = is64;
    }
}

__global__ void k_zero() {
    int i = blockIdx.x * blockDim.x + threadIdx.x;
    if (i < NN) { g_deg[i] = 0.0f; g_indeg[i] = 0; }
}

__global__ void k_count(const void* ei, int E) {
    int e = blockIdx.x * blockDim.x + threadIdx.x;
    if (e < E) {
        int s, d;
        load_edge(ei, E, e, s, d);
        atomicAdd(&g_deg[s], 1.0f);
        atomicAdd(&g_indeg[d], 1);
    }
}

__global__ void k_dinv() {
    int i = blockIdx.x * blockDim.x + threadIdx.x;
    if (i < NN) {
        float dg = g_deg[i];
        g_dinv[i] = (dg > 0.0f) ? rsqrtf(fmaxf(dg, 1.0f)) : 0.0f;
    }
}

__global__ void k_scan1() {
    __shared__ int sh[512];
    int gid = blockIdx.x * 512 + threadIdx.x;
    int v = (gid < NN) ? g_indeg[gid] : 0;
    sh[threadIdx.x] = v;
    __syncthreads();
    for (int off = 1; off < 512; off <<= 1) {
        int t = (threadIdx.x >= off) ? sh[threadIdx.x - off] : 0;
        __syncthreads();
        sh[threadIdx.x] += t;
        __syncthreads();
    }
    if (gid <= NN) g_ptr[gid] = sh[threadIdx.x] - v;   // exclusive
    if (threadIdx.x == 511) g_bsums[blockIdx.x] = sh[511];
}

__global__ void k_scan2(int nb) {
    if (threadIdx.x == 0 && blockIdx.x == 0) {
        int acc = 0;
        for (int i = 0; i < nb; i++) { int t = g_bsums[i]; g_bsums[i] = acc; acc += t; }
    }
}

__global__ void k_scan3() {
    int gid = blockIdx.x * 512 + threadIdx.x;
    if (gid <= NN) {
        int p = g_ptr[gid] + g_bsums[blockIdx.x];
        g_ptr[gid] = p;
        if (gid < NN) g_fill[gid] = p;
    }
}

__global__ void k_scatter(const void* ei, int E) {
    int e = blockIdx.x * blockDim.x + threadIdx.x;
    if (e < E) {
        int s, d;
        load_edge(ei, E, e, s, d);
        float w = -(g_dinv[s] * g_dinv[d]);
        int pos = atomicAdd(&g_fill[d], 1);
        g_src[pos] = s;
        g_w[pos] = w;
    }
}

// ------------------------- layer-1 sparse (F=3) -------------------------
// y = prop(X)            when subc < 0
// y = 2*prop(X) - SUB    otherwise
__global__ void k_spmm3(const float* __restrict__ x, int xc, int yc, int subc) {
    int i = blockIdx.x * blockDim.x + threadIdx.x;
    if (i >= NN) return;
    const float* X = (xc == 0) ? x : (xc == 1) ? g_t1 : (xc == 2) ? g_t2 : g_t3;
    float*       Y = (yc == 1) ? g_t1 : (yc == 2) ? g_t2 : g_t3;
    int b = g_ptr[i], en = g_ptr[i + 1];
    float a0 = 0, a1 = 0, a2 = 0;
    for (int e = b; e < en; e++) {
        int s = g_src[e];
        float ww = g_w[e];
        const float* xr = X + 3 * s;
        a0 = fmaf(ww, xr[0], a0);
        a1 = fmaf(ww, xr[1], a1);
        a2 = fmaf(ww, xr[2], a2);
    }
    float* y = Y + 3 * i;
    if (subc < 0) {
        y[0] = a0; y[1] = a1; y[2] = a2;
    } else {
        const float* S = (subc == 0) ? x : (subc == 1) ? g_t1 : (subc == 2) ? g_t2 : g_t3;
        y[0] = 2.0f * a0 - S[3 * i + 0];
        y[1] = 2.0f * a1 - S[3 * i + 1];
        y[2] = 2.0f * a2 - S[3 * i + 2];
    }
}

// ------------------------- F=128 SpMM (pull, warp per node) -------------------------
// reads segment xseg of Tcat, writes yseg; if subseg >= 0: y = 2*acc - sub
__global__ void __launch_bounds__(256) k_spmm128(int xseg, int yseg, int subseg) {
    int node = blockIdx.x * 8 + (threadIdx.x >> 5);
    if (node >= NN) return;
    int lane = threadIdx.x & 31;
    int b = g_ptr[node], en = g_ptr[node + 1];
    float4 acc = make_float4(0, 0, 0, 0);
    const float* Xbase = g_Tcat + xseg * 128 + (size_t)0;
    for (int e = b; e < en; e++) {
        int s = __ldg(&g_src[e]);
        float ww = __ldg(&g_w[e]);
        float4 v = *(const float4*)(Xbase + (size_t)s * 512 + lane * 4);
        acc.x = fmaf(ww, v.x, acc.x);
        acc.y = fmaf(ww, v.y, acc.y);
        acc.z = fmaf(ww, v.z, acc.z);
        acc.w = fmaf(ww, v.w, acc.w);
    }
    float* yrow = g_Tcat + (size_t)node * 512 + yseg * 128 + lane * 4;
    if (subseg >= 0) {
        const float4 sv = *(const float4*)(g_Tcat + (size_t)node * 512 + subseg * 128 + lane * 4);
        acc.x = 2.0f * acc.x - sv.x;
        acc.y = 2.0f * acc.y - sv.y;
        acc.z = 2.0f * acc.z - sv.z;
        acc.w = 2.0f * acc.w - sv.w;
    }
    *(float4*)yrow = acc;
}

// ------------------------- layer-1 GEMM (12 x 128) -------------------------
__global__ void __launch_bounds__(256) k_gemm1(const float* __restrict__ x,
                                               const float* __restrict__ W1,
                                               const float* __restrict__ b1) {
    __shared__ float shW[12 * 128];
    __shared__ float shT[32 * 12];
    int tid = threadIdx.x;
    for (int i = tid; i < 1536; i += 256) shW[i] = W1[i];
    int r0 = blockIdx.x * 32;
    for (int i = tid; i < 384; i += 256) {
        int r = i / 12, j = i % 12;
        int k = j / 3, d = j % 3;
        int gr = r0 + r;
        float v = 0.0f;
        if (gr < NN) {
            const float* src = (k == 0) ? x : (k == 1) ? g_t1 : (k == 2) ? g_t2 : g_t3;
            v = src[gr * 3 + d];
        }
        shT[i] = v;
    }
    __syncthreads();
    int r = tid >> 3;
    int c0 = (tid & 7) * 16;
    int gr = r0 + r;
    if (gr < NN) {
        #pragma unroll
        for (int c = c0; c < c0 + 16; c++) {
            float acc = b1[c];
            #pragma unroll
            for (int j = 0; j < 12; j++) acc = fmaf(shT[r * 12 + j], shW[j * 128 + c], acc);
            g_H[(size_t)gr * 128 + c] = acc;
        }
    }
}

// ------------------------- main GEMM: Tcat (N x 512) @ W (512 x 128) -------------------------
__global__ void __launch_bounds__(256) k_gemm512(const float* __restrict__ B,
                                                 const float* __restrict__ bias) {
    __shared__ float As[16][128];
    __shared__ float Bs[16][128];
    int tid = threadIdx.x;
    int row0 = blockIdx.x * 128;
    int ty = tid >> 4, tx = tid & 15;
    float acc[8][8];
    #pragma unroll
    for (int i = 0; i < 8; i++)
        #pragma unroll
        for (int j = 0; j < 8; j++) acc[i][j] = 0.0f;

    for (int k0 = 0; k0 < 512; k0 += 16) {
        #pragma unroll
        for (int q = 0; q < 2; q++) {
            int idx = tid * 2 + q;           // 0..511
            int r = idx >> 2;                // 0..127
            int kq = (idx & 3) * 4;
            int grow = row0 + r;
            float4 v = make_float4(0, 0, 0, 0);
            if (grow < NN) v = *(const float4*)&g_Tcat[(size_t)grow * 512 + k0 + kq];
            As[kq + 0][r] = v.x;
            As[kq + 1][r] = v.y;
            As[kq + 2][r] = v.z;
            As[kq + 3][r] = v.w;
        }
        #pragma unroll
        for (int q = 0; q < 2; q++) {
            int idx = tid * 2 + q;           // 0..511
            int r = idx >> 5;                // 0..15
            int c = (idx & 31) * 4;          // 0..124
            *(float4*)&Bs[r][c] = *(const float4*)&B[(k0 + r) * 128 + c];
        }
        __syncthreads();
        #pragma unroll
        for (int kk = 0; kk < 16; kk++) {
            float a[8], bb[8];
            #pragma unroll
            for (int i = 0; i < 8; i++) a[i] = As[kk][ty * 8 + i];
            #pragma unroll
            for (int j = 0; j < 8; j++) bb[j] = Bs[kk][tx * 8 + j];
            #pragma unroll
            for (int i = 0; i < 8; i++)
                #pragma unroll
                for (int j = 0; j < 8; j++) acc[i][j] = fmaf(a[i], bb[j], acc[i][j]);
        }
        __syncthreads();
    }
    #pragma unroll
    for (int i = 0; i < 8; i++) {
        int gr = row0 + ty * 8 + i;
        if (gr < NN) {
            #pragma unroll
            for (int j = 0; j < 8; j += 4) {
                int c = tx * 8 + j;
                float4 o;
                o.x = acc[i][j + 0] + bias[c + 0];
                o.y = acc[i][j + 1] + bias[c + 1];
                o.z = acc[i][j + 2] + bias[c + 2];
                o.w = acc[i][j + 3] + bias[c + 3];
                *(float4*)&g_H[(size_t)gr * 128 + c] = o;
            }
        }
    }
}

// ------------------------- BN (two-pass deterministic) -------------------------
__device__ __forceinline__ float apply_act(float v, int act) {
    return act ? fmaxf(v, 0.0f) : (v >= 0.0f ? v : NEG * v);
}

__global__ void __launch_bounds__(128) k_colstat1(int act) {
    int c = threadIdx.x;
    float s = 0.0f, s2 = 0.0f;
    for (int r = blockIdx.x; r < NN; r += NSTAT) {
        float v = g_H[(size_t)r * 128 + c];
        v = apply_act(v, act);
        s += v;
        s2 = fmaf(v, v, s2);
    }
    g_part[blockIdx.x * 256 + c] = s;
    g_part[blockIdx.x * 256 + 128 + c] = s2;
}

__global__ void __launch_bounds__(128) k_colstat2(const float* __restrict__ gamma,
                                                  const float* __restrict__ beta) {
    int c = threadIdx.x;
    float s = 0.0f, s2 = 0.0f;
    for (int b = 0; b < NSTAT; b++) {
        s += g_part[b * 256 + c];
        s2 += g_part[b * 256 + 128 + c];
    }
    float mu = s / (float)NN;
    float var = s2 / (float)NN - mu * mu;
    float sc = gamma[c] * rsqrtf(var + BN_EPS);
    g_scale[c] = sc;
    g_shift[c] = beta[c] - mu * sc;
}

__global__ void __launch_bounds__(256) k_bnapply(int act) {
    int idx = blockIdx.x * blockDim.x + threadIdx.x;
    if (idx < NN * 128) {
        int c = idx & 127;
        int r = idx >> 7;
        float v = apply_act(g_H[idx], act);
        g_Tcat[(size_t)r * 512 + c] = fmaf(v, g_scale[c], g_shift[c]);
    }
}

// ------------------------- final: L2 norm + head -------------------------
__global__ void __launch_bounds__(256) k_final(const float* __restrict__ Wrep,
                                               const float* __restrict__ brep,
                                               float* __restrict__ out) {
    __shared__ float shW[384];
    int tid = threadIdx.x;
    for (int i = tid; i < 384; i += 256) shW[i] = Wrep[i];
    __syncthreads();
    int node = blockIdx.x * 8 + (tid >> 5);
    int lane = tid & 31;
    if (node >= NN) return;
    float4 h = *(const float4*)&g_H[(size_t)node * 128 + lane * 4];
    float hv[4] = {h.x, h.y, h.z, h.w};
    float ss = 0.0f, p0 = 0.0f, p1 = 0.0f, p2 = 0.0f;
    #pragma unroll
    for (int q = 0; q < 4; q++) {
        int f = lane * 4 + q;
        ss = fmaf(hv[q], hv[q], ss);
        p0 = fmaf(hv[q], shW[f * 3 + 0], p0);
        p1 = fmaf(hv[q], shW[f * 3 + 1], p1);
        p2 = fmaf(hv[q], shW[f * 3 + 2], p2);
    }
    #pragma unroll
    for (int o = 16; o > 0; o >>= 1) {
        ss += __shfl_xor_sync(0xFFFFFFFFu, ss, o);
        p0 += __shfl_xor_sync(0xFFFFFFFFu, p0, o);
        p1 += __shfl_xor_sync(0xFFFFFFFFu, p1, o);
        p2 += __shfl_xor_sync(0xFFFFFFFFu, p2, o);
    }
    if (lane == 0) {
        float inv = 1.0f / fmaxf(sqrtf(ss), L2_EPS);
        out[node * 3 + 0] = fmaf(p0, inv, brep[0]);
        out[node * 3 + 1] = fmaf(p1, inv, brep[1]);
        out[node * 3 + 2] = fmaf(p2, inv, brep[2]);
    }
}

// ------------------------- host -------------------------
extern "C" void kernel_launch(void* const* d_in, const int* in_sizes, int n_in,
                              void* d_out, int out_size) {
    const float* x    = (const float*)d_in[0];
    const void*  ei   = d_in[1];
    const float* W1   = (const float*)d_in[2];
    const float* b1   = (const float*)d_in[3];
    const float* W2   = (const float*)d_in[4];
    const float* b2   = (const float*)d_in[5];
    const float* W3   = (const float*)d_in[6];
    const float* b3   = (const float*)d_in[7];
    const float* W4   = (const float*)d_in[8];
    const float* b4   = (const float*)d_in[9];
    const float* g1   = (const float*)d_in[10];
    const float* be1  = (const float*)d_in[11];
    const float* g2   = (const float*)d_in[12];
    const float* be2  = (const float*)d_in[13];
    const float* g3   = (const float*)d_in[14];
    const float* be3  = (const float*)d_in[15];
    const float* Wrep = (const float*)d_in[16];
    const float* brep = (const float*)d_in[17];
    float* out = (float*)d_out;

    int E = in_sizes[1] / 2;
    if (E > EE) E = EE;

    const int TB = 256;
    int gN = (NN + TB - 1) / TB;
    int gE = (E + TB - 1) / TB;
    int gWarp = (NN + 7) / 8;       // warp-per-node kernels, 8 warps/block
    int gScan = (NN + 1 + 511) / 512;

    // ---- graph structure ----
    k_detect<<<1, 32>>>((const int*)ei);
    k_zero<<<gN, TB>>>();
    k_count<<<gE, TB>>>(ei, E);
    k_dinv<<<gN, TB>>>();
    k_scan1<<<gScan, 512>>>();
    k_scan2<<<1, 1>>>(gScan);
    k_scan3<<<gScan, 512>>>();
    k_scatter<<<gE, TB>>>(ei, E);

    // ---- layer 1 (F=3) ----
    k_spmm3<<<gN, TB>>>(x, 0, 1, -1);   // t1 = prop(x)
    k_spmm3<<<gN, TB>>>(x, 1, 2, 0);    // t2 = 2*prop(t1) - x
    k_spmm3<<<gN, TB>>>(x, 2, 3, 1);    // t3 = 2*prop(t2) - t1
    k_gemm1<<<(NN + 31) / 32, 256>>>(x, W1, b1);
    k_colstat1<<<NSTAT, 128>>>(0);
    k_colstat2<<<1, 128>>>(g1, be1);
    k_bnapply<<<(NN * 128 + TB - 1) / TB, TB>>>(0);

    int gGemm = (NN + 127) / 128;

    // ---- layer 2 ----
    k_spmm128<<<gWarp, 256>>>(0, 1, -1);
    k_spmm128<<<gWarp, 256>>>(1, 2, 0);
    k_spmm128<<<gWarp, 256>>>(2, 3, 1);
    k_gemm512<<<gGemm, 256>>>(W2, b2);
    k_colstat1<<<NSTAT, 128>>>(0);
    k_colstat2<<<1, 128>>>(g2, be2);
    k_bnapply<<<(NN * 128 + TB - 1) / TB, TB>>>(0);

    // ---- layer 3 ----
    k_spmm128<<<gWarp, 256>>>(0, 1, -1);
    k_spmm128<<<gWarp, 256>>>(1, 2, 0);
    k_spmm128<<<gWarp, 256>>>(2, 3, 1);
    k_gemm512<<<gGemm, 256>>>(W3, b3);
    k_colstat1<<<NSTAT, 128>>>(1);      // relu
    k_colstat2<<<1, 128>>>(g3, be3);
    k_bnapply<<<(NN * 128 + TB - 1) / TB, TB>>>(1);

    // ---- layer 4 ----
    k_spmm128<<<gWarp, 256>>>(0, 1, -1);
    k_spmm128<<<gWarp, 256>>>(1, 2, 0);
    k_spmm128<<<gWarp, 256>>>(2, 3, 1);
    k_gemm512<<<gGemm, 256>>>(W4, b4);

    // ---- L2 norm + representation head ----
    k_final<<<gWarp, 256>>>(Wrep, brep, out);
}

// round 3
// speedup vs baseline: 1.5145x; 1.5145x over previous
#include <cuda_runtime.h>
#include <cuda_bf16.h>
#include <math.h>
#include <stdint.h>

#define NN 100000
#define EE 1600000
#define HID 128
#define NEG 0.01f
#define BN_EPS 1e-5f
#define L2_EPS 1e-12f
#define NSTAT 512

// ------------------------- device scratch -------------------------
__device__ float g_Tcat[(size_t)NN * 512];   // [Tx0|Tx1|Tx2|Tx3] per row
__device__ float g_H[(size_t)NN * 128];      // GEMM output (pre-activation)
__device__ float g_t1[NN * 3];
__device__ float g_t2[NN * 3];
__device__ float g_t3[NN * 3];
__device__ float g_deg[NN];
__device__ float g_dinv[NN];
__device__ int   g_indeg[NN];
__device__ int   g_ptr[NN + 1];
__device__ int   g_fill[NN];
__device__ int   g_bsums[256];
__device__ int2  g_edge[EE];                 // (src, w-as-int) CSR by dst
__device__ float g_part[NSTAT * 256];
__device__ float g_scale[128];
__device__ float g_shift[128];
__device__ uint32_t g_Wbhi[256 * 128];       // W packed bf16x2 along K: hi part
__device__ uint32_t g_Wblo[256 * 128];       // lo part
__device__ int   g_is64;

// ------------------------- helpers -------------------------
__device__ __forceinline__ uint32_t smem_u32(const void* p) {
    uint32_t a;
    asm("{ .reg .u64 t; cvta.to.shared.u64 t, %1; cvt.u32.u64 %0, t; }" : "=r"(a) : "l"(p));
    return a;
}

// split two floats into packed-bf16x2 hi and lo (x = hi + lo + O(2^-18 x))
__device__ __forceinline__ void split2(float x0, float x1, uint32_t& hi, uint32_t& lo) {
    __nv_bfloat16 h0 = __float2bfloat16_rn(x0);
    __nv_bfloat16 h1 = __float2bfloat16_rn(x1);
    float r0 = x0 - __bfloat162float(h0);
    float r1 = x1 - __bfloat162float(h1);
    __nv_bfloat162 H;
    H.x = h0; H.y = h1;
    hi = *reinterpret_cast<uint32_t*>(&H);
    __nv_bfloat162 L = __floats2bfloat162_rn(r0, r1);
    lo = *reinterpret_cast<uint32_t*>(&L);
}

#define MMA16816(c, a, b0, b1) \
    asm volatile("mma.sync.aligned.m16n8k16.row.col.f32.bf16.bf16.f32 " \
        "{%0,%1,%2,%3}, {%4,%5,%6,%7}, {%8,%9}, {%0,%1,%2,%3};" \
        : "+f"((c)[0]), "+f"((c)[1]), "+f"((c)[2]), "+f"((c)[3]) \
        : "r"((a)[0]), "r"((a)[1]), "r"((a)[2]), "r"((a)[3]), "r"(b0), "r"(b1))

__device__ __forceinline__ void cp16(uint32_t sdst, const void* gsrc) {
    asm volatile("cp.async.ca.shared.global [%0], [%1], 16;" :: "r"(sdst), "l"(gsrc) : "memory");
}

// ------------------------- edge helpers -------------------------
__device__ __forceinline__ void load_edge(const void* ei, int E, int e, int& s, int& d) {
    if (g_is64) {
        const long long* p = (const long long*)ei;
        s = (int)p[e];
        d = (int)p[(size_t)E + e];
    } else {
        const int* p = (const int*)ei;
        s = p[e];
        d = p[E + e];
    }
}

// ------------------------- setup kernels -------------------------
__global__ void k_detect(const int* ei32) {
    if (threadIdx.x == 0 && blockIdx.x == 0) {
        int is64 = 1;
        for (int i = 0; i < 32; i++) {
            if (ei32[2 * i + 1] != 0) { is64 = 0; break; }
        }
        g_is64 = is64;
    }
}

__global__ void k_zero() {
    int i = blockIdx.x * blockDim.x + threadIdx.x;
    if (i < NN) { g_deg[i] = 0.0f; g_indeg[i] = 0; }
}

__global__ void k_count(const void* ei, int E) {
    int e = blockIdx.x * blockDim.x + threadIdx.x;
    if (e < E) {
        int s, d;
        load_edge(ei, E, e, s, d);
        atomicAdd(&g_deg[s], 1.0f);
        atomicAdd(&g_indeg[d], 1);
    }
}

__global__ void k_dinv() {
    int i = blockIdx.x * blockDim.x + threadIdx.x;
    if (i < NN) {
        float dg = g_deg[i];
        g_dinv[i] = (dg > 0.0f) ? rsqrtf(fmaxf(dg, 1.0f)) : 0.0f;
    }
}

__global__ void k_scan1() {
    __shared__ int sh[512];
    int gid = blockIdx.x * 512 + threadIdx.x;
    int v = (gid < NN) ? g_indeg[gid] : 0;
    sh[threadIdx.x] = v;
    __syncthreads();
    for (int off = 1; off < 512; off <<= 1) {
        int t = (threadIdx.x >= off) ? sh[threadIdx.x - off] : 0;
        __syncthreads();
        sh[threadIdx.x] += t;
        __syncthreads();
    }
    if (gid <= NN) g_ptr[gid] = sh[threadIdx.x] - v;
    if (threadIdx.x == 511) g_bsums[blockIdx.x] = sh[511];
}

__global__ void k_scan2(int nb) {
    if (threadIdx.x == 0 && blockIdx.x == 0) {
        int acc = 0;
        for (int i = 0; i < nb; i++) { int t = g_bsums[i]; g_bsums[i] = acc; acc += t; }
    }
}

__global__ void k_scan3() {
    int gid = blockIdx.x * 512 + threadIdx.x;
    if (gid <= NN) {
        int p = g_ptr[gid] + g_bsums[blockIdx.x];
        g_ptr[gid] = p;
        if (gid < NN) g_fill[gid] = p;
    }
}

__global__ void k_scatter(const void* ei, int E) {
    int e = blockIdx.x * blockDim.x + threadIdx.x;
    if (e < E) {
        int s, d;
        load_edge(ei, E, e, s, d);
        float w = -(g_dinv[s] * g_dinv[d]);
        int pos = atomicAdd(&g_fill[d], 1);
        g_edge[pos] = make_int2(s, __float_as_int(w));
    }
}

// ------------------------- layer-1 sparse (F=3) -------------------------
__global__ void k_spmm3(const float* __restrict__ x, int xc, int yc, int subc) {
    int i = blockIdx.x * blockDim.x + threadIdx.x;
    if (i >= NN) return;
    const float* X = (xc == 0) ? x : (xc == 1) ? g_t1 : (xc == 2) ? g_t2 : g_t3;
    float*       Y = (yc == 1) ? g_t1 : (yc == 2) ? g_t2 : g_t3;
    int b = g_ptr[i], en = g_ptr[i + 1];
    float a0 = 0, a1 = 0, a2 = 0;
    for (int e = b; e < en; e++) {
        int2 ed = __ldg(&g_edge[e]);
        float ww = __int_as_float(ed.y);
        const float* xr = X + 3 * ed.x;
        a0 = fmaf(ww, xr[0], a0);
        a1 = fmaf(ww, xr[1], a1);
        a2 = fmaf(ww, xr[2], a2);
    }
    float* y = Y + 3 * i;
    if (subc < 0) {
        y[0] = a0; y[1] = a1; y[2] = a2;
    } else {
        const float* S = (subc == 0) ? x : (subc == 1) ? g_t1 : (subc == 2) ? g_t2 : g_t3;
        y[0] = 2.0f * a0 - S[3 * i + 0];
        y[1] = 2.0f * a1 - S[3 * i + 1];
        y[2] = 2.0f * a2 - S[3 * i + 2];
    }
}

// ------------------------- F=128 SpMM (pull, warp per node) -------------------------
__global__ void __launch_bounds__(256) k_spmm128(int xseg, int yseg, int subseg) {
    int node = blockIdx.x * 8 + (threadIdx.x >> 5);
    if (node >= NN) return;
    int lane = threadIdx.x & 31;
    int b = g_ptr[node], en = g_ptr[node + 1];
    float4 acc = make_float4(0, 0, 0, 0);
    const float* Xbase = g_Tcat + xseg * 128;
    for (int e = b; e < en; e++) {
        int2 ed = __ldg(&g_edge[e]);
        float ww = __int_as_float(ed.y);
        float4 v = *(const float4*)(Xbase + (size_t)ed.x * 512 + lane * 4);
        acc.x = fmaf(ww, v.x, acc.x);
        acc.y = fmaf(ww, v.y, acc.y);
        acc.z = fmaf(ww, v.z, acc.z);
        acc.w = fmaf(ww, v.w, acc.w);
    }
    float* yrow = g_Tcat + (size_t)node * 512 + yseg * 128 + lane * 4;
    if (subseg >= 0) {
        const float4 sv = *(const float4*)(g_Tcat + (size_t)node * 512 + subseg * 128 + lane * 4);
        acc.x = 2.0f * acc.x - sv.x;
        acc.y = 2.0f * acc.y - sv.y;
        acc.z = 2.0f * acc.z - sv.z;
        acc.w = 2.0f * acc.w - sv.w;
    }
    *(float4*)yrow = acc;
}

// ------------------------- layer-1 GEMM (12 x 128) -------------------------
__global__ void __launch_bounds__(256) k_gemm1(const float* __restrict__ x,
                                               const float* __restrict__ W1,
                                               const float* __restrict__ b1) {
    __shared__ float shW[12 * 128];
    __shared__ float shT[32 * 12];
    int tid = threadIdx.x;
    for (int i = tid; i < 1536; i += 256) shW[i] = W1[i];
    int r0 = blockIdx.x * 32;
    for (int i = tid; i < 384; i += 256) {
        int r = i / 12, j = i % 12;
        int k = j / 3, d = j % 3;
        int gr = r0 + r;
        float v = 0.0f;
        if (gr < NN) {
            const float* src = (k == 0) ? x : (k == 1) ? g_t1 : (k == 2) ? g_t2 : g_t3;
            v = src[gr * 3 + d];
        }
        shT[i] = v;
    }
    __syncthreads();
    int r = tid >> 3;
    int c0 = (tid & 7) * 16;
    int gr = r0 + r;
    if (gr < NN) {
        #pragma unroll
        for (int c = c0; c < c0 + 16; c++) {
            float acc = b1[c];
            #pragma unroll
            for (int j = 0; j < 12; j++) acc = fmaf(shT[r * 12 + j], shW[j * 128 + c], acc);
            g_H[(size_t)gr * 128 + c] = acc;
        }
    }
}

// ------------------------- weight prep: split W[512][128] into bf16 hi/lo packed along K ----
__global__ void k_prepw(const float* __restrict__ W) {
    int i = blockIdx.x * 256 + threadIdx.x;     // 0..32767 : kp = i>>7, n = i&127
    if (i < 256 * 128) {
        int kp = i >> 7, n = i & 127;
        float x0 = W[(2 * kp) * 128 + n];
        float x1 = W[(2 * kp + 1) * 128 + n];
        uint32_t hi, lo;
        split2(x0, x1, hi, lo);
        g_Wbhi[i] = hi;
        g_Wblo[i] = lo;
    }
}

// ------------------------- bf16 split-precision mma.sync GEMM -------------------------
// C[N x 128] = Tcat[N x 512] @ W[512 x 128], 3-term bf16 hi/lo split.
#define AST 20                         // uint stride of A smem row (16 + 4 pad)
#define BST 136                        // uint stride of B smem row (128 + 8 pad)
#define A_UINTS (128 * AST)            // 2560
#define B_UINTS (16 * BST)             // 2176
#define STAGE_UINTS (2 * A_UINTS + 2 * B_UINTS)   // 9472
#define SMEM_GEMM (2 * STAGE_UINTS * 4)           // 75776 B

__global__ void __launch_bounds__(256, 2) k_gemm_bf(const float* __restrict__ bias) {
    extern __shared__ uint32_t sm[];
    const int tid = threadIdx.x;
    const int lane = tid & 31;
    const int wid = tid >> 5;
    const int wm = wid & 3;            // warp m position (4)
    const int wn = wid >> 2;           // warp n position (2)
    const int lk = lane & 3;
    const int lr = lane >> 2;
    const int row0 = blockIdx.x * 128;
    const uint32_t sbase = smem_u32(sm);

    float acc[2][8][4];
    #pragma unroll
    for (int mt = 0; mt < 2; mt++)
        #pragma unroll
        for (int nt = 0; nt < 8; nt++)
            #pragma unroll
            for (int q = 0; q < 4; q++) acc[mt][nt][q] = 0.0f;

    float4 areg[4];

    // ---- prologue: B chunk 0 via cp.async, A chunk 0 via ldg+convert ----
    {
        uint32_t bh_s = sbase + (2 * A_UINTS) * 4;
        uint32_t bl_s = bh_s + B_UINTS * 4;
        #pragma unroll
        for (int j = 0; j < 2; j++) {
            int q = tid * 2 + j;
            int kp = q >> 5, n4 = (q & 31) * 4;
            cp16(bh_s + (kp * BST + n4) * 4, &g_Wbhi[kp * 128 + n4]);
            cp16(bl_s + (kp * BST + n4) * 4, &g_Wblo[kp * 128 + n4]);
        }
        asm volatile("cp.async.commit_group;" ::: "memory");
        #pragma unroll
        for (int i = 0; i < 4; i++) {
            int idx = tid + (i << 8);
            int r = idx >> 3, kq = (idx & 7) << 2;
            int gr = row0 + r;
            areg[i] = (gr < NN) ? *(const float4*)&g_Tcat[(size_t)gr * 512 + kq]
                                : make_float4(0, 0, 0, 0);
        }
        uint32_t* Ah = sm;
        uint32_t* Al = sm + A_UINTS;
        #pragma unroll
        for (int i = 0; i < 4; i++) {
            int idx = tid + (i << 8);
            int r = idx >> 3, kq = (idx & 7) << 2;
            uint32_t h0, l0, h1, l1;
            split2(areg[i].x, areg[i].y, h0, l0);
            split2(areg[i].z, areg[i].w, h1, l1);
            uint32_t* d = Ah + r * AST + (kq >> 1);
            d[0] = h0; d[1] = h1;
            uint32_t* dl = Al + r * AST + (kq >> 1);
            dl[0] = l0; dl[1] = l1;
        }
        asm volatile("cp.async.wait_group 0;" ::: "memory");
        __syncthreads();
    }

    for (int c = 0; c < 16; c++) {
        int st = c & 1;
        int nst = st ^ 1;
        // issue next-chunk loads
        if (c < 15) {
            uint32_t bh_s = sbase + (nst * STAGE_UINTS + 2 * A_UINTS) * 4;
            uint32_t bl_s = bh_s + B_UINTS * 4;
            int kbase = (c + 1) * 16;
            #pragma unroll
            for (int j = 0; j < 2; j++) {
                int q = tid * 2 + j;
                int kp = q >> 5, n4 = (q & 31) * 4;
                cp16(bh_s + (kp * BST + n4) * 4, &g_Wbhi[(kbase + kp) * 128 + n4]);
                cp16(bl_s + (kp * BST + n4) * 4, &g_Wblo[(kbase + kp) * 128 + n4]);
            }
            asm volatile("cp.async.commit_group;" ::: "memory");
            int k0 = (c + 1) * 32;
            #pragma unroll
            for (int i = 0; i < 4; i++) {
                int idx = tid + (i << 8);
                int r = idx >> 3, kq = (idx & 7) << 2;
                int gr = row0 + r;
                areg[i] = (gr < NN) ? *(const float4*)&g_Tcat[(size_t)gr * 512 + k0 + kq]
                                    : make_float4(0, 0, 0, 0);
            }
        }

        // ---- compute current stage ----
        {
            const uint32_t* Ah = sm + st * STAGE_UINTS;
            const uint32_t* Al = Ah + A_UINTS;
            const uint32_t* Bh = Al + A_UINTS;
            const uint32_t* Bl = Bh + B_UINTS;
            #pragma unroll
            for (int ks = 0; ks < 2; ks++) {
                int kpb = ks * 8;
                uint32_t ah[2][4], al[2][4];
                #pragma unroll
                for (int mt = 0; mt < 2; mt++) {
                    int r = wm * 32 + mt * 16 + lr;
                    const uint32_t* A0 = Ah + r * AST + kpb + lk;
                    ah[mt][0] = A0[0];
                    ah[mt][1] = A0[8 * AST];
                    ah[mt][2] = A0[4];
                    ah[mt][3] = A0[8 * AST + 4];
                    const uint32_t* A1 = Al + r * AST + kpb + lk;
                    al[mt][0] = A1[0];
                    al[mt][1] = A1[8 * AST];
                    al[mt][2] = A1[4];
                    al[mt][3] = A1[8 * AST + 4];
                }
                #pragma unroll
                for (int nt = 0; nt < 8; nt++) {
                    int col = wn * 64 + nt * 8 + lr;
                    const uint32_t* B0 = Bh + (kpb + lk) * BST + col;
                    uint32_t bh0 = B0[0], bh1 = B0[4 * BST];
                    const uint32_t* B1 = Bl + (kpb + lk) * BST + col;
                    uint32_t bl0 = B1[0], bl1 = B1[4 * BST];
                    #pragma unroll
                    for (int mt = 0; mt < 2; mt++) {
                        MMA16816(acc[mt][nt], ah[mt], bh0, bh1);
                        MMA16816(acc[mt][nt], ah[mt], bl0, bl1);
                        MMA16816(acc[mt][nt], al[mt], bh0, bh1);
                    }
                }
            }
        }

        // ---- stage next-chunk A into smem ----
        if (c < 15) {
            uint32_t* Ah = sm + nst * STAGE_UINTS;
            uint32_t* Al = Ah + A_UINTS;
            #pragma unroll
            for (int i = 0; i < 4; i++) {
                int idx = tid + (i << 8);
                int r = idx >> 3, kq = (idx & 7) << 2;
                uint32_t h0, l0, h1, l1;
                split2(areg[i].x, areg[i].y, h0, l0);
                split2(areg[i].z, areg[i].w, h1, l1);
                uint32_t* d = Ah + r * AST + (kq >> 1);
                d[0] = h0; d[1] = h1;
                uint32_t* dl = Al + r * AST + (kq >> 1);
                dl[0] = l0; dl[1] = l1;
            }
            asm volatile("cp.async.wait_group 0;" ::: "memory");
        }
        __syncthreads();
    }

    // ---- epilogue ----
    #pragma unroll
    for (int mt = 0; mt < 2; mt++) {
        int r1 = row0 + wm * 32 + mt * 16 + lr;
        int r2 = r1 + 8;
        #pragma unroll
        for (int nt = 0; nt < 8; nt++) {
            int col = wn * 64 + nt * 8 + 2 * lk;
            float2 bs = *(const float2*)&bias[col];
            if (r1 < NN) {
                float2 o;
                o.x = acc[mt][nt][0] + bs.x;
                o.y = acc[mt][nt][1] + bs.y;
                *(float2*)&g_H[(size_t)r1 * 128 + col] = o;
            }
            if (r2 < NN) {
                float2 o;
                o.x = acc[mt][nt][2] + bs.x;
                o.y = acc[mt][nt][3] + bs.y;
                *(float2*)&g_H[(size_t)r2 * 128 + col] = o;
            }
        }
    }
}

// ------------------------- BN (two-pass deterministic) -------------------------
__device__ __forceinline__ float apply_act(float v, int act) {
    return act ? fmaxf(v, 0.0f) : (v >= 0.0f ? v : NEG * v);
}

__global__ void __launch_bounds__(128) k_colstat1(int act) {
    int c = threadIdx.x;
    float s = 0.0f, s2 = 0.0f;
    for (int r = blockIdx.x; r < NN; r += NSTAT) {
        float v = g_H[(size_t)r * 128 + c];
        v = apply_act(v, act);
        s += v;
        s2 = fmaf(v, v, s2);
    }
    g_part[blockIdx.x * 256 + c] = s;
    g_part[blockIdx.x * 256 + 128 + c] = s2;
}

__global__ void __launch_bounds__(128) k_colstat2(const float* __restrict__ gamma,
                                                  const float* __restrict__ beta) {
    int c = threadIdx.x;
    float s = 0.0f, s2 = 0.0f;
    for (int b = 0; b < NSTAT; b++) {
        s += g_part[b * 256 + c];
        s2 += g_part[b * 256 + 128 + c];
    }
    float mu = s / (float)NN;
    float var = s2 / (float)NN - mu * mu;
    float sc = gamma[c] * rsqrtf(var + BN_EPS);
    g_scale[c] = sc;
    g_shift[c] = beta[c] - mu * sc;
}

__global__ void __launch_bounds__(256) k_bnapply(int act) {
    int idx = blockIdx.x * blockDim.x + threadIdx.x;
    if (idx < NN * 128) {
        int c = idx & 127;
        int r = idx >> 7;
        float v = apply_act(g_H[idx], act);
        g_Tcat[(size_t)r * 512 + c] = fmaf(v, g_scale[c], g_shift[c]);
    }
}

// ------------------------- final: L2 norm + head -------------------------
__global__ void __launch_bounds__(256) k_final(const float* __restrict__ Wrep,
                                               const float* __restrict__ brep,
                                               float* __restrict__ out) {
    __shared__ float shW[384];
    int tid = threadIdx.x;
    for (int i = tid; i < 384; i += 256) shW[i] = Wrep[i];
    __syncthreads();
    int node = blockIdx.x * 8 + (tid >> 5);
    int lane = tid & 31;
    if (node >= NN) return;
    float4 h = *(const float4*)&g_H[(size_t)node * 128 + lane * 4];
    float hv[4] = {h.x, h.y, h.z, h.w};
    float ss = 0.0f, p0 = 0.0f, p1 = 0.0f, p2 = 0.0f;
    #pragma unroll
    for (int q = 0; q < 4; q++) {
        int f = lane * 4 + q;
        ss = fmaf(hv[q], hv[q], ss);
        p0 = fmaf(hv[q], shW[f * 3 + 0], p0);
        p1 = fmaf(hv[q], shW[f * 3 + 1], p1);
        p2 = fmaf(hv[q], shW[f * 3 + 2], p2);
    }
    #pragma unroll
    for (int o = 16; o > 0; o >>= 1) {
        ss += __shfl_xor_sync(0xFFFFFFFFu, ss, o);
        p0 += __shfl_xor_sync(0xFFFFFFFFu, p0, o);
        p1 += __shfl_xor_sync(0xFFFFFFFFu, p1, o);
        p2 += __shfl_xor_sync(0xFFFFFFFFu, p2, o);
    }
    if (lane == 0) {
        float inv = 1.0f / fmaxf(sqrtf(ss), L2_EPS);
        out[node * 3 + 0] = fmaf(p0, inv, brep[0]);
        out[node * 3 + 1] = fmaf(p1, inv, brep[1]);
        out[node * 3 + 2] = fmaf(p2, inv, brep[2]);
    }
}

// ------------------------- host -------------------------
extern "C" void kernel_launch(void* const* d_in, const int* in_sizes, int n_in,
                              void* d_out, int out_size) {
    const float* x    = (const float*)d_in[0];
    const void*  ei   = d_in[1];
    const float* W1   = (const float*)d_in[2];
    const float* b1   = (const float*)d_in[3];
    const float* W2   = (const float*)d_in[4];
    const float* b2   = (const float*)d_in[5];
    const float* W3   = (const float*)d_in[6];
    const float* b3   = (const float*)d_in[7];
    const float* W4   = (const float*)d_in[8];
    const float* b4   = (const float*)d_in[9];
    const float* g1   = (const float*)d_in[10];
    const float* be1  = (const float*)d_in[11];
    const float* g2   = (const float*)d_in[12];
    const float* be2  = (const float*)d_in[13];
    const float* g3   = (const float*)d_in[14];
    const float* be3  = (const float*)d_in[15];
    const float* Wrep = (const float*)d_in[16];
    const float* brep = (const float*)d_in[17];
    float* out = (float*)d_out;

    int E = in_sizes[1] / 2;
    if (E > EE) E = EE;

    static int s_attr_done = 0;
    if (!s_attr_done) {
        cudaFuncSetAttribute(k_gemm_bf, cudaFuncAttributeMaxDynamicSharedMemorySize, SMEM_GEMM);
        s_attr_done = 1;
    }

    const int TB = 256;
    int gN = (NN + TB - 1) / TB;
    int gE = (E + TB - 1) / TB;
    int gWarp = (NN + 7) / 8;
    int gScan = (NN + 1 + 511) / 512;
    int gGemm = (NN + 127) / 128;

    // ---- graph structure ----
    k_detect<<<1, 32>>>((const int*)ei);
    k_zero<<<gN, TB>>>();
    k_count<<<gE, TB>>>(ei, E);
    k_dinv<<<gN, TB>>>();
    k_scan1<<<gScan, 512>>>();
    k_scan2<<<1, 1>>>(gScan);
    k_scan3<<<gScan, 512>>>();
    k_scatter<<<gE, TB>>>(ei, E);

    // ---- layer 1 (F=3) ----
    k_spmm3<<<gN, TB>>>(x, 0, 1, -1);
    k_spmm3<<<gN, TB>>>(x, 1, 2, 0);
    k_spmm3<<<gN, TB>>>(x, 2, 3, 1);
    k_gemm1<<<(NN + 31) / 32, 256>>>(x, W1, b1);
    k_colstat1<<<NSTAT, 128>>>(0);
    k_colstat2<<<1, 128>>>(g1, be1);
    k_bnapply<<<(NN * 128 + TB - 1) / TB, TB>>>(0);

    // ---- layer 2 ----
    k_spmm128<<<gWarp, 256>>>(0, 1, -1);
    k_spmm128<<<gWarp, 256>>>(1, 2, 0);
    k_spmm128<<<gWarp, 256>>>(2, 3, 1);
    k_prepw<<<128, 256>>>(W2);
    k_gemm_bf<<<gGemm, 256, SMEM_GEMM>>>(b2);
    k_colstat1<<<NSTAT, 128>>>(0);
    k_colstat2<<<1, 128>>>(g2, be2);
    k_bnapply<<<(NN * 128 + TB - 1) / TB, TB>>>(0);

    // ---- layer 3 ----
    k_spmm128<<<gWarp, 256>>>(0, 1, -1);
    k_spmm128<<<gWarp, 256>>>(1, 2, 0);
    k_spmm128<<<gWarp, 256>>>(2, 3, 1);
    k_prepw<<<128, 256>>>(W3);
    k_gemm_bf<<<gGemm, 256, SMEM_GEMM>>>(b3);
    k_colstat1<<<NSTAT, 128>>>(1);
    k_colstat2<<<1, 128>>>(g3, be3);
    k_bnapply<<<(NN * 128 + TB - 1) / TB, TB>>>(1);

    // ---- layer 4 ----
    k_spmm128<<<gWarp, 256>>>(0, 1, -1);
    k_spmm128<<<gWarp, 256>>>(1, 2, 0);
    k_spmm128<<<gWarp, 256>>>(2, 3, 1);
    k_prepw<<<128, 256>>>(W4);
    k_gemm_bf<<<gGemm, 256, SMEM_GEMM>>>(b4);

    // ---- L2 norm + representation head ----
    k_final<<<gWarp, 256>>>(Wrep, brep, out);
}

// round 4
// speedup vs baseline: 1.6241x; 1.0724x over previous
#include <cuda_runtime.h>
#include <cuda_bf16.h>
#include <cuda_fp16.h>
#include <math.h>
#include <stdint.h>

#define NN 100000
#define EE 1600000
#define HID 128
#define NEG 0.01f
#define BN_EPS 1e-5f
#define L2_EPS 1e-12f
#define NSTAT 512

// ------------------------- device scratch -------------------------
__device__ float g_Tcat[(size_t)NN * 512];     // [Tx0|Tx1|Tx2|Tx3] fp32 per row (GEMM operand)
__device__ uint32_t g_Thalf[(size_t)NN * 256]; // same, fp16 packed (SpMM gather operand); 4 segs x 64 half2
__device__ float g_H[(size_t)NN * 128];        // GEMM output (pre-activation)
__device__ float g_t1[NN * 3];
__device__ float g_t2[NN * 3];
__device__ float g_t3[NN * 3];
__device__ float g_deg[NN];
__device__ float g_dinv[NN];
__device__ int   g_indeg[NN];
__device__ int   g_ptr[NN + 1];
__device__ int   g_fill[NN];
__device__ int   g_bsums[256];
__device__ int2  g_edge[EE];                   // (src, w-as-int) CSR by dst
__device__ float g_part[NSTAT * 256];
__device__ float g_scale[128];
__device__ float g_shift[128];
__device__ uint32_t g_Wbhi[256 * 128];         // W packed bf16x2 along K: hi part
__device__ uint32_t g_Wblo[256 * 128];         // lo part
__device__ int   g_is64;

// ------------------------- helpers -------------------------
__device__ __forceinline__ uint32_t smem_u32(const void* p) {
    uint32_t a;
    asm("{ .reg .u64 t; cvta.to.shared.u64 t, %1; cvt.u32.u64 %0, t; }" : "=r"(a) : "l"(p));
    return a;
}

// split two floats into packed-bf16x2 hi and lo (x = hi + lo + O(2^-18 x))
__device__ __forceinline__ void split2(float x0, float x1, uint32_t& hi, uint32_t& lo) {
    __nv_bfloat16 h0 = __float2bfloat16_rn(x0);
    __nv_bfloat16 h1 = __float2bfloat16_rn(x1);
    float r0 = x0 - __bfloat162float(h0);
    float r1 = x1 - __bfloat162float(h1);
    __nv_bfloat162 H;
    H.x = h0; H.y = h1;
    hi = *reinterpret_cast<uint32_t*>(&H);
    __nv_bfloat162 L = __floats2bfloat162_rn(r0, r1);
    lo = *reinterpret_cast<uint32_t*>(&L);
}

__device__ __forceinline__ uint32_t packh2(float a, float b) {
    __half2 h = __floats2half2_rn(a, b);
    return *reinterpret_cast<uint32_t*>(&h);
}

#define MMA16816(c, a, b0, b1) \
    asm volatile("mma.sync.aligned.m16n8k16.row.col.f32.bf16.bf16.f32 " \
        "{%0,%1,%2,%3}, {%4,%5,%6,%7}, {%8,%9}, {%0,%1,%2,%3};" \
        : "+f"((c)[0]), "+f"((c)[1]), "+f"((c)[2]), "+f"((c)[3]) \
        : "r"((a)[0]), "r"((a)[1]), "r"((a)[2]), "r"((a)[3]), "r"(b0), "r"(b1))

__device__ __forceinline__ void cp16(uint32_t sdst, const void* gsrc) {
    asm volatile("cp.async.ca.shared.global [%0], [%1], 16;" :: "r"(sdst), "l"(gsrc) : "memory");
}

// ------------------------- edge helpers -------------------------
__device__ __forceinline__ void load_edge(const void* ei, int E, int e, int& s, int& d) {
    if (g_is64) {
        const long long* p = (const long long*)ei;
        s = (int)p[e];
        d = (int)p[(size_t)E + e];
    } else {
        const int* p = (const int*)ei;
        s = p[e];
        d = p[E + e];
    }
}

// ------------------------- setup kernels -------------------------
__global__ void k_detect(const int* ei32) {
    if (threadIdx.x == 0 && blockIdx.x == 0) {
        int is64 = 1;
        for (int i = 0; i < 32; i++) {
            if (ei32[2 * i + 1] != 0) { is64 = 0; break; }
        }
        g_is64 = is64;
    }
}

__global__ void k_zero() {
    int i = blockIdx.x * blockDim.x + threadIdx.x;
    if (i < NN) { g_deg[i] = 0.0f; g_indeg[i] = 0; }
}

__global__ void k_count(const void* ei, int E) {
    int e = blockIdx.x * blockDim.x + threadIdx.x;
    if (e < E) {
        int s, d;
        load_edge(ei, E, e, s, d);
        atomicAdd(&g_deg[s], 1.0f);
        atomicAdd(&g_indeg[d], 1);
    }
}

__global__ void k_dinv() {
    int i = blockIdx.x * blockDim.x + threadIdx.x;
    if (i < NN) {
        float dg = g_deg[i];
        g_dinv[i] = (dg > 0.0f) ? rsqrtf(fmaxf(dg, 1.0f)) : 0.0f;
    }
}

__global__ void k_scan1() {
    __shared__ int sh[512];
    int gid = blockIdx.x * 512 + threadIdx.x;
    int v = (gid < NN) ? g_indeg[gid] : 0;
    sh[threadIdx.x] = v;
    __syncthreads();
    for (int off = 1; off < 512; off <<= 1) {
        int t = (threadIdx.x >= off) ? sh[threadIdx.x - off] : 0;
        __syncthreads();
        sh[threadIdx.x] += t;
        __syncthreads();
    }
    if (gid <= NN) g_ptr[gid] = sh[threadIdx.x] - v;
    if (threadIdx.x == 511) g_bsums[blockIdx.x] = sh[511];
}

__global__ void k_scan2(int nb) {
    if (threadIdx.x == 0 && blockIdx.x == 0) {
        int acc = 0;
        for (int i = 0; i < nb; i++) { int t = g_bsums[i]; g_bsums[i] = acc; acc += t; }
    }
}

__global__ void k_scan3() {
    int gid = blockIdx.x * 512 + threadIdx.x;
    if (gid <= NN) {
        int p = g_ptr[gid] + g_bsums[blockIdx.x];
        g_ptr[gid] = p;
        if (gid < NN) g_fill[gid] = p;
    }
}

__global__ void k_scatter(const void* ei, int E) {
    int e = blockIdx.x * blockDim.x + threadIdx.x;
    if (e < E) {
        int s, d;
        load_edge(ei, E, e, s, d);
        float w = -(g_dinv[s] * g_dinv[d]);
        int pos = atomicAdd(&g_fill[d], 1);
        g_edge[pos] = make_int2(s, __float_as_int(w));
    }
}

// ------------------------- layer-1 sparse (F=3) -------------------------
__global__ void k_spmm3(const float* __restrict__ x, int xc, int yc, int subc) {
    int i = blockIdx.x * blockDim.x + threadIdx.x;
    if (i >= NN) return;
    const float* X = (xc == 0) ? x : (xc == 1) ? g_t1 : (xc == 2) ? g_t2 : g_t3;
    float*       Y = (yc == 1) ? g_t1 : (yc == 2) ? g_t2 : g_t3;
    int b = g_ptr[i], en = g_ptr[i + 1];
    float a0 = 0, a1 = 0, a2 = 0;
    for (int e = b; e < en; e++) {
        int2 ed = __ldg(&g_edge[e]);
        float ww = __int_as_float(ed.y);
        const float* xr = X + 3 * ed.x;
        a0 = fmaf(ww, xr[0], a0);
        a1 = fmaf(ww, xr[1], a1);
        a2 = fmaf(ww, xr[2], a2);
    }
    float* y = Y + 3 * i;
    if (subc < 0) {
        y[0] = a0; y[1] = a1; y[2] = a2;
    } else {
        const float* S = (subc == 0) ? x : (subc == 1) ? g_t1 : (subc == 2) ? g_t2 : g_t3;
        y[0] = 2.0f * a0 - S[3 * i + 0];
        y[1] = 2.0f * a1 - S[3 * i + 1];
        y[2] = 2.0f * a2 - S[3 * i + 2];
    }
}

// ------------------------- F=128 SpMM: fp16 gather, fp32 accumulate -------------------------
// gathers xseg from g_Thalf; writes yseg to g_Tcat (fp32) and (if yseg<3) g_Thalf (fp16).
// if subseg >= 0: y = 2*acc - Tcat[subseg] (fp32 exact).
__global__ void __launch_bounds__(256) k_spmm128h(int xseg, int yseg, int subseg) {
    int node = blockIdx.x * 8 + (threadIdx.x >> 5);
    if (node >= NN) return;
    int lane = threadIdx.x & 31;
    int b = g_ptr[node], en = g_ptr[node + 1];
    float4 acc = make_float4(0, 0, 0, 0);
    const uint32_t xoff = xseg * 64 + lane * 2;
    for (int e = b; e < en; e++) {
        int2 ed = __ldg(&g_edge[e]);
        float ww = __int_as_float(ed.y);
        uint2 v = __ldg((const uint2*)(g_Thalf + (size_t)ed.x * 256 + xoff));
        float2 f0 = __half22float2(*reinterpret_cast<__half2*>(&v.x));
        float2 f1 = __half22float2(*reinterpret_cast<__half2*>(&v.y));
        acc.x = fmaf(ww, f0.x, acc.x);
        acc.y = fmaf(ww, f0.y, acc.y);
        acc.z = fmaf(ww, f1.x, acc.z);
        acc.w = fmaf(ww, f1.y, acc.w);
    }
    if (subseg >= 0) {
        const float4 sv = *(const float4*)(g_Tcat + (size_t)node * 512 + subseg * 128 + lane * 4);
        acc.x = 2.0f * acc.x - sv.x;
        acc.y = 2.0f * acc.y - sv.y;
        acc.z = 2.0f * acc.z - sv.z;
        acc.w = 2.0f * acc.w - sv.w;
    }
    *(float4*)(g_Tcat + (size_t)node * 512 + yseg * 128 + lane * 4) = acc;
    if (yseg < 3) {
        uint2 o;
        o.x = packh2(acc.x, acc.y);
        o.y = packh2(acc.z, acc.w);
        *(uint2*)(g_Thalf + (size_t)node * 256 + yseg * 64 + lane * 2) = o;
    }
}

// ------------------------- layer-1 GEMM (12 x 128) -------------------------
__global__ void __launch_bounds__(256) k_gemm1(const float* __restrict__ x,
                                               const float* __restrict__ W1,
                                               const float* __restrict__ b1) {
    __shared__ float shW[12 * 128];
    __shared__ float shT[32 * 12];
    int tid = threadIdx.x;
    for (int i = tid; i < 1536; i += 256) shW[i] = W1[i];
    int r0 = blockIdx.x * 32;
    for (int i = tid; i < 384; i += 256) {
        int r = i / 12, j = i % 12;
        int k = j / 3, d = j % 3;
        int gr = r0 + r;
        float v = 0.0f;
        if (gr < NN) {
            const float* src = (k == 0) ? x : (k == 1) ? g_t1 : (k == 2) ? g_t2 : g_t3;
            v = src[gr * 3 + d];
        }
        shT[i] = v;
    }
    __syncthreads();
    int r = tid >> 3;
    int c0 = (tid & 7) * 16;
    int gr = r0 + r;
    if (gr < NN) {
        #pragma unroll
        for (int c = c0; c < c0 + 16; c++) {
            float acc = b1[c];
            #pragma unroll
            for (int j = 0; j < 12; j++) acc = fmaf(shT[r * 12 + j], shW[j * 128 + c], acc);
            g_H[(size_t)gr * 128 + c] = acc;
        }
    }
}

// ------------------------- weight prep: split W[512][128] into bf16 hi/lo packed along K ----
__global__ void k_prepw(const float* __restrict__ W) {
    int i = blockIdx.x * 256 + threadIdx.x;
    if (i < 256 * 128) {
        int kp = i >> 7, n = i & 127;
        float x0 = W[(2 * kp) * 128 + n];
        float x1 = W[(2 * kp + 1) * 128 + n];
        uint32_t hi, lo;
        split2(x0, x1, hi, lo);
        g_Wbhi[i] = hi;
        g_Wblo[i] = lo;
    }
}

// ------------------------- bf16 split-precision mma.sync GEMM -------------------------
#define AST 20
#define BST 136
#define A_UINTS (128 * AST)
#define B_UINTS (16 * BST)
#define STAGE_UINTS (2 * A_UINTS + 2 * B_UINTS)
#define SMEM_GEMM (2 * STAGE_UINTS * 4)

__global__ void __launch_bounds__(256, 2) k_gemm_bf(const float* __restrict__ bias) {
    extern __shared__ uint32_t sm[];
    const int tid = threadIdx.x;
    const int lane = tid & 31;
    const int wid = tid >> 5;
    const int wm = wid & 3;
    const int wn = wid >> 2;
    const int lk = lane & 3;
    const int lr = lane >> 2;
    const int row0 = blockIdx.x * 128;
    const uint32_t sbase = smem_u32(sm);

    float acc[2][8][4];
    #pragma unroll
    for (int mt = 0; mt < 2; mt++)
        #pragma unroll
        for (int nt = 0; nt < 8; nt++)
            #pragma unroll
            for (int q = 0; q < 4; q++) acc[mt][nt][q] = 0.0f;

    float4 areg[4];

    {
        uint32_t bh_s = sbase + (2 * A_UINTS) * 4;
        uint32_t bl_s = bh_s + B_UINTS * 4;
        #pragma unroll
        for (int j = 0; j < 2; j++) {
            int q = tid * 2 + j;
            int kp = q >> 5, n4 = (q & 31) * 4;
            cp16(bh_s + (kp * BST + n4) * 4, &g_Wbhi[kp * 128 + n4]);
            cp16(bl_s + (kp * BST + n4) * 4, &g_Wblo[kp * 128 + n4]);
        }
        asm volatile("cp.async.commit_group;" ::: "memory");
        #pragma unroll
        for (int i = 0; i < 4; i++) {
            int idx = tid + (i << 8);
            int r = idx >> 3, kq = (idx & 7) << 2;
            int gr = row0 + r;
            areg[i] = (gr < NN) ? *(const float4*)&g_Tcat[(size_t)gr * 512 + kq]
                                : make_float4(0, 0, 0, 0);
        }
        uint32_t* Ah = sm;
        uint32_t* Al = sm + A_UINTS;
        #pragma unroll
        for (int i = 0; i < 4; i++) {
            int idx = tid + (i << 8);
            int r = idx >> 3, kq = (idx & 7) << 2;
            uint32_t h0, l0, h1, l1;
            split2(areg[i].x, areg[i].y, h0, l0);
            split2(areg[i].z, areg[i].w, h1, l1);
            uint32_t* d = Ah + r * AST + (kq >> 1);
            d[0] = h0; d[1] = h1;
            uint32_t* dl = Al + r * AST + (kq >> 1);
            dl[0] = l0; dl[1] = l1;
        }
        asm volatile("cp.async.wait_group 0;" ::: "memory");
        __syncthreads();
    }

    for (int c = 0; c < 16; c++) {
        int st = c & 1;
        int nst = st ^ 1;
        if (c < 15) {
            uint32_t bh_s = sbase + (nst * STAGE_UINTS + 2 * A_UINTS) * 4;
            uint32_t bl_s = bh_s + B_UINTS * 4;
            int kbase = (c + 1) * 16;
            #pragma unroll
            for (int j = 0; j < 2; j++) {
                int q = tid * 2 + j;
                int kp = q >> 5, n4 = (q & 31) * 4;
                cp16(bh_s + (kp * BST + n4) * 4, &g_Wbhi[(kbase + kp) * 128 + n4]);
                cp16(bl_s + (kp * BST + n4) * 4, &g_Wblo[(kbase + kp) * 128 + n4]);
            }
            asm volatile("cp.async.commit_group;" ::: "memory");
            int k0 = (c + 1) * 32;
            #pragma unroll
            for (int i = 0; i < 4; i++) {
                int idx = tid + (i << 8);
                int r = idx >> 3, kq = (idx & 7) << 2;
                int gr = row0 + r;
                areg[i] = (gr < NN) ? *(const float4*)&g_Tcat[(size_t)gr * 512 + k0 + kq]
                                    : make_float4(0, 0, 0, 0);
            }
        }

        {
            const uint32_t* Ah = sm + st * STAGE_UINTS;
            const uint32_t* Al = Ah + A_UINTS;
            const uint32_t* Bh = Al + A_UINTS;
            const uint32_t* Bl = Bh + B_UINTS;
            #pragma unroll
            for (int ks = 0; ks < 2; ks++) {
                int kpb = ks * 8;
                uint32_t ah[2][4], al[2][4];
                #pragma unroll
                for (int mt = 0; mt < 2; mt++) {
                    int r = wm * 32 + mt * 16 + lr;
                    const uint32_t* A0 = Ah + r * AST + kpb + lk;
                    ah[mt][0] = A0[0];
                    ah[mt][1] = A0[8 * AST];
                    ah[mt][2] = A0[4];
                    ah[mt][3] = A0[8 * AST + 4];
                    const uint32_t* A1 = Al + r * AST + kpb + lk;
                    al[mt][0] = A1[0];
                    al[mt][1] = A1[8 * AST];
                    al[mt][2] = A1[4];
                    al[mt][3] = A1[8 * AST + 4];
                }
                #pragma unroll
                for (int nt = 0; nt < 8; nt++) {
                    int col = wn * 64 + nt * 8 + lr;
                    const uint32_t* B0 = Bh + (kpb + lk) * BST + col;
                    uint32_t bh0 = B0[0], bh1 = B0[4 * BST];
                    const uint32_t* B1 = Bl + (kpb + lk) * BST + col;
                    uint32_t bl0 = B1[0], bl1 = B1[4 * BST];
                    #pragma unroll
                    for (int mt = 0; mt < 2; mt++) {
                        MMA16816(acc[mt][nt], ah[mt], bh0, bh1);
                        MMA16816(acc[mt][nt], ah[mt], bl0, bl1);
                        MMA16816(acc[mt][nt], al[mt], bh0, bh1);
                    }
                }
            }
        }

        if (c < 15) {
            uint32_t* Ah = sm + nst * STAGE_UINTS;
            uint32_t* Al = Ah + A_UINTS;
            #pragma unroll
            for (int i = 0; i < 4; i++) {
                int idx = tid + (i << 8);
                int r = idx >> 3, kq = (idx & 7) << 2;
                uint32_t h0, l0, h1, l1;
                split2(areg[i].x, areg[i].y, h0, l0);
                split2(areg[i].z, areg[i].w, h1, l1);
                uint32_t* d = Ah + r * AST + (kq >> 1);
                d[0] = h0; d[1] = h1;
                uint32_t* dl = Al + r * AST + (kq >> 1);
                dl[0] = l0; dl[1] = l1;
            }
            asm volatile("cp.async.wait_group 0;" ::: "memory");
        }
        __syncthreads();
    }

    #pragma unroll
    for (int mt = 0; mt < 2; mt++) {
        int r1 = row0 + wm * 32 + mt * 16 + lr;
        int r2 = r1 + 8;
        #pragma unroll
        for (int nt = 0; nt < 8; nt++) {
            int col = wn * 64 + nt * 8 + 2 * lk;
            float2 bs = *(const float2*)&bias[col];
            if (r1 < NN) {
                float2 o;
                o.x = acc[mt][nt][0] + bs.x;
                o.y = acc[mt][nt][1] + bs.y;
                *(float2*)&g_H[(size_t)r1 * 128 + col] = o;
            }
            if (r2 < NN) {
                float2 o;
                o.x = acc[mt][nt][2] + bs.x;
                o.y = acc[mt][nt][3] + bs.y;
                *(float2*)&g_H[(size_t)r2 * 128 + col] = o;
            }
        }
    }
}

// ------------------------- BN (two-pass deterministic) -------------------------
__device__ __forceinline__ float apply_act(float v, int act) {
    return act ? fmaxf(v, 0.0f) : (v >= 0.0f ? v : NEG * v);
}

__global__ void __launch_bounds__(128) k_colstat1(int act) {
    int c = threadIdx.x;
    float s = 0.0f, s2 = 0.0f;
    for (int r = blockIdx.x; r < NN; r += NSTAT) {
        float v = g_H[(size_t)r * 128 + c];
        v = apply_act(v, act);
        s += v;
        s2 = fmaf(v, v, s2);
    }
    g_part[blockIdx.x * 256 + c] = s;
    g_part[blockIdx.x * 256 + 128 + c] = s2;
}

__global__ void __launch_bounds__(128) k_colstat2(const float* __restrict__ gamma,
                                                  const float* __restrict__ beta) {
    int c = threadIdx.x;
    float s = 0.0f, s2 = 0.0f;
    for (int b = 0; b < NSTAT; b++) {
        s += g_part[b * 256 + c];
        s2 += g_part[b * 256 + 128 + c];
    }
    float mu = s / (float)NN;
    float var = s2 / (float)NN - mu * mu;
    float sc = gamma[c] * rsqrtf(var + BN_EPS);
    g_scale[c] = sc;
    g_shift[c] = beta[c] - mu * sc;
}

// writes BN output to Tcat seg0 (fp32) and Thalf seg0 (fp16); one thread per half2
__global__ void __launch_bounds__(256) k_bnapply(int act) {
    int idx = blockIdx.x * blockDim.x + threadIdx.x;
    if (idx < NN * 64) {
        int p = idx & 63;
        int r = idx >> 6;
        int c = p * 2;
        float2 h = *(const float2*)&g_H[(size_t)r * 128 + c];
        float v0 = fmaf(apply_act(h.x, act), g_scale[c],     g_shift[c]);
        float v1 = fmaf(apply_act(h.y, act), g_scale[c + 1], g_shift[c + 1]);
        *(float2*)&g_Tcat[(size_t)r * 512 + c] = make_float2(v0, v1);
        g_Thalf[(size_t)r * 256 + p] = packh2(v0, v1);
    }
}

// layer-1 entry: x,t1,t2,t3 (F=3 each) are consumed by k_gemm1 directly; but layer-2's
// first prop gathers seg0 of Thalf — produced by k_bnapply. Nothing extra needed.

// ------------------------- final: L2 norm + head -------------------------
__global__ void __launch_bounds__(256) k_final(const float* __restrict__ Wrep,
                                               const float* __restrict__ brep,
                                               float* __restrict__ out) {
    __shared__ float shW[384];
    int tid = threadIdx.x;
    for (int i = tid; i < 384; i += 256) shW[i] = Wrep[i];
    __syncthreads();
    int node = blockIdx.x * 8 + (tid >> 5);
    int lane = tid & 31;
    if (node >= NN) return;
    float4 h = *(const float4*)&g_H[(size_t)node * 128 + lane * 4];
    float hv[4] = {h.x, h.y, h.z, h.w};
    float ss = 0.0f, p0 = 0.0f, p1 = 0.0f, p2 = 0.0f;
    #pragma unroll
    for (int q = 0; q < 4; q++) {
        int f = lane * 4 + q;
        ss = fmaf(hv[q], hv[q], ss);
        p0 = fmaf(hv[q], shW[f * 3 + 0], p0);
        p1 = fmaf(hv[q], shW[f * 3 + 1], p1);
        p2 = fmaf(hv[q], shW[f * 3 + 2], p2);
    }
    #pragma unroll
    for (int o = 16; o > 0; o >>= 1) {
        ss += __shfl_xor_sync(0xFFFFFFFFu, ss, o);
        p0 += __shfl_xor_sync(0xFFFFFFFFu, p0, o);
        p1 += __shfl_xor_sync(0xFFFFFFFFu, p1, o);
        p2 += __shfl_xor_sync(0xFFFFFFFFu, p2, o);
    }
    if (lane == 0) {
        float inv = 1.0f / fmaxf(sqrtf(ss), L2_EPS);
        out[node * 3 + 0] = fmaf(p0, inv, brep[0]);
        out[node * 3 + 1] = fmaf(p1, inv, brep[1]);
        out[node * 3 + 2] = fmaf(p2, inv, brep[2]);
    }
}

// ------------------------- host -------------------------
extern "C" void kernel_launch(void* const* d_in, const int* in_sizes, int n_in,
                              void* d_out, int out_size) {
    const float* x    = (const float*)d_in[0];
    const void*  ei   = d_in[1];
    const float* W1   = (const float*)d_in[2];
    const float* b1   = (const float*)d_in[3];
    const float* W2   = (const float*)d_in[4];
    const float* b2   = (const float*)d_in[5];
    const float* W3   = (const float*)d_in[6];
    const float* b3   = (const float*)d_in[7];
    const float* W4   = (const float*)d_in[8];
    const float* b4   = (const float*)d_in[9];
    const float* g1   = (const float*)d_in[10];
    const float* be1  = (const float*)d_in[11];
    const float* g2   = (const float*)d_in[12];
    const float* be2  = (const float*)d_in[13];
    const float* g3   = (const float*)d_in[14];
    const float* be3  = (const float*)d_in[15];
    const float* Wrep = (const float*)d_in[16];
    const float* brep = (const float*)d_in[17];
    float* out = (float*)d_out;

    int E = in_sizes[1] / 2;
    if (E > EE) E = EE;

    static int s_attr_done = 0;
    if (!s_attr_done) {
        cudaFuncSetAttribute(k_gemm_bf, cudaFuncAttributeMaxDynamicSharedMemorySize, SMEM_GEMM);
        s_attr_done = 1;
    }

    const int TB = 256;
    int gN = (NN + TB - 1) / TB;
    int gE = (E + TB - 1) / TB;
    int gWarp = (NN + 7) / 8;
    int gScan = (NN + 1 + 511) / 512;
    int gGemm = (NN + 127) / 128;
    int gBN = (NN * 64 + TB - 1) / TB;

    // ---- graph structure ----
    k_detect<<<1, 32>>>((const int*)ei);
    k_zero<<<gN, TB>>>();
    k_count<<<gE, TB>>>(ei, E);
    k_dinv<<<gN, TB>>>();
    k_scan1<<<gScan, 512>>>();
    k_scan2<<<1, 1>>>(gScan);
    k_scan3<<<gScan, 512>>>();
    k_scatter<<<gE, TB>>>(ei, E);

    // ---- layer 1 (F=3) ----
    k_spmm3<<<gN, TB>>>(x, 0, 1, -1);
    k_spmm3<<<gN, TB>>>(x, 1, 2, 0);
    k_spmm3<<<gN, TB>>>(x, 2, 3, 1);
    k_gemm1<<<(NN + 31) / 32, 256>>>(x, W1, b1);
    k_colstat1<<<NSTAT, 128>>>(0);
    k_colstat2<<<1, 128>>>(g1, be1);
    k_bnapply<<<gBN, TB>>>(0);

    // ---- layer 2 ----
    k_spmm128h<<<gWarp, 256>>>(0, 1, -1);
    k_spmm128h<<<gWarp, 256>>>(1, 2, 0);
    k_spmm128h<<<gWarp, 256>>>(2, 3, 1);
    k_prepw<<<128, 256>>>(W2);
    k_gemm_bf<<<gGemm, 256, SMEM_GEMM>>>(b2);
    k_colstat1<<<NSTAT, 128>>>(0);
    k_colstat2<<<1, 128>>>(g2, be2);
    k_bnapply<<<gBN, TB>>>(0);

    // ---- layer 3 ----
    k_spmm128h<<<gWarp, 256>>>(0, 1, -1);
    k_spmm128h<<<gWarp, 256>>>(1, 2, 0);
    k_spmm128h<<<gWarp, 256>>>(2, 3, 1);
    k_prepw<<<128, 256>>>(W3);
    k_gemm_bf<<<gGemm, 256, SMEM_GEMM>>>(b3);
    k_colstat1<<<NSTAT, 128>>>(1);
    k_colstat2<<<1, 128>>>(g3, be3);
    k_bnapply<<<gBN, TB>>>(1);

    // ---- layer 4 ----
    k_spmm128h<<<gWarp, 256>>>(0, 1, -1);
    k_spmm128h<<<gWarp, 256>>>(1, 2, 0);
    k_spmm128h<<<gWarp, 256>>>(2, 3, 1);
    k_prepw<<<128, 256>>>(W4);
    k_gemm_bf<<<gGemm, 256, SMEM_GEMM>>>(b4);

    // ---- L2 norm + representation head ----
    k_final<<<gWarp, 256>>>(Wrep, brep, out);
}

// round 5
// speedup vs baseline: 1.6658x; 1.0257x over previous
#include <cuda_runtime.h>
#include <cuda_bf16.h>
#include <cuda_fp16.h>
#include <math.h>
#include <stdint.h>

#define NN 100000
#define EE 1600000
#define HID 128
#define NEG 0.01f
#define BN_EPS 1e-5f
#define L2_EPS 1e-12f
#define NSTAT 512

// ------------------------- device scratch -------------------------
__device__ float g_Tcat[(size_t)NN * 512];     // [Tx0|Tx1|Tx2|Tx3] fp32 per row (GEMM operand)
__device__ uint32_t g_Thalf[(size_t)NN * 256]; // same, fp16 packed; 4 segs x 64 half2 per row
__device__ float g_H[(size_t)NN * 128];        // GEMM output (pre-activation)
__device__ float g_t1[NN * 3];
__device__ float g_t2[NN * 3];
__device__ float g_t3[NN * 3];
__device__ float g_deg[NN];
__device__ float g_dinv[NN];
__device__ int   g_indeg[NN];
__device__ int   g_ptr[NN + 1];
__device__ int   g_fill[NN];
__device__ int   g_bsums[256];
__device__ int2  g_edge[EE];                   // (src, w-as-int) CSR by dst
__device__ float g_part[NSTAT * 256];
__device__ float g_scale[128];
__device__ float g_shift[128];
__device__ uint32_t g_Wbhi[256 * 128];         // W packed bf16x2 along K: hi part
__device__ uint32_t g_Wblo[256 * 128];         // lo part
__device__ int   g_is64;

// ------------------------- helpers -------------------------
__device__ __forceinline__ uint32_t smem_u32(const void* p) {
    uint32_t a;
    asm("{ .reg .u64 t; cvta.to.shared.u64 t, %1; cvt.u32.u64 %0, t; }" : "=r"(a) : "l"(p));
    return a;
}

__device__ __forceinline__ void split2(float x0, float x1, uint32_t& hi, uint32_t& lo) {
    __nv_bfloat16 h0 = __float2bfloat16_rn(x0);
    __nv_bfloat16 h1 = __float2bfloat16_rn(x1);
    float r0 = x0 - __bfloat162float(h0);
    float r1 = x1 - __bfloat162float(h1);
    __nv_bfloat162 H;
    H.x = h0; H.y = h1;
    hi = *reinterpret_cast<uint32_t*>(&H);
    __nv_bfloat162 L = __floats2bfloat162_rn(r0, r1);
    lo = *reinterpret_cast<uint32_t*>(&L);
}

__device__ __forceinline__ uint32_t packh2(float a, float b) {
    __half2 h = __floats2half2_rn(a, b);
    return *reinterpret_cast<uint32_t*>(&h);
}

#define MMA16816(c, a, b0, b1) \
    asm volatile("mma.sync.aligned.m16n8k16.row.col.f32.bf16.bf16.f32 " \
        "{%0,%1,%2,%3}, {%4,%5,%6,%7}, {%8,%9}, {%0,%1,%2,%3};" \
        : "+f"((c)[0]), "+f"((c)[1]), "+f"((c)[2]), "+f"((c)[3]) \
        : "r"((a)[0]), "r"((a)[1]), "r"((a)[2]), "r"((a)[3]), "r"(b0), "r"(b1))

__device__ __forceinline__ void cp16(uint32_t sdst, const void* gsrc) {
    asm volatile("cp.async.ca.shared.global [%0], [%1], 16;" :: "r"(sdst), "l"(gsrc) : "memory");
}

// accumulate 8 fp16 features (uint4 = 4 half2) scaled by w into acc[8]
__device__ __forceinline__ void acc8(float* acc, uint4 v, float w) {
    float2 f0 = __half22float2(*reinterpret_cast<__half2*>(&v.x));
    float2 f1 = __half22float2(*reinterpret_cast<__half2*>(&v.y));
    float2 f2 = __half22float2(*reinterpret_cast<__half2*>(&v.z));
    float2 f3 = __half22float2(*reinterpret_cast<__half2*>(&v.w));
    acc[0] = fmaf(w, f0.x, acc[0]);
    acc[1] = fmaf(w, f0.y, acc[1]);
    acc[2] = fmaf(w, f1.x, acc[2]);
    acc[3] = fmaf(w, f1.y, acc[3]);
    acc[4] = fmaf(w, f2.x, acc[4]);
    acc[5] = fmaf(w, f2.y, acc[5]);
    acc[6] = fmaf(w, f3.x, acc[6]);
    acc[7] = fmaf(w, f3.y, acc[7]);
}

// ------------------------- edge helpers -------------------------
__device__ __forceinline__ void load_edge(const void* ei, int E, int e, int& s, int& d) {
    if (g_is64) {
        const long long* p = (const long long*)ei;
        s = (int)p[e];
        d = (int)p[(size_t)E + e];
    } else {
        const int* p = (const int*)ei;
        s = p[e];
        d = p[E + e];
    }
}

// ------------------------- setup kernels -------------------------
__global__ void k_detect(const int* ei32) {
    if (threadIdx.x == 0 && blockIdx.x == 0) {
        int is64 = 1;
        for (int i = 0; i < 32; i++) {
            if (ei32[2 * i + 1] != 0) { is64 = 0; break; }
        }
        g_is64 = is64;
    }
}

__global__ void k_zero() {
    int i = blockIdx.x * blockDim.x + threadIdx.x;
    if (i < NN) { g_deg[i] = 0.0f; g_indeg[i] = 0; }
}

__global__ void k_count(const void* ei, int E) {
    int e = blockIdx.x * blockDim.x + threadIdx.x;
    if (e < E) {
        int s, d;
        load_edge(ei, E, e, s, d);
        atomicAdd(&g_deg[s], 1.0f);
        atomicAdd(&g_indeg[d], 1);
    }
}

__global__ void k_dinv() {
    int i = blockIdx.x * blockDim.x + threadIdx.x;
    if (i < NN) {
        float dg = g_deg[i];
        g_dinv[i] = (dg > 0.0f) ? rsqrtf(fmaxf(dg, 1.0f)) : 0.0f;
    }
}

__global__ void k_scan1() {
    __shared__ int sh[512];
    int gid = blockIdx.x * 512 + threadIdx.x;
    int v = (gid < NN) ? g_indeg[gid] : 0;
    sh[threadIdx.x] = v;
    __syncthreads();
    for (int off = 1; off < 512; off <<= 1) {
        int t = (threadIdx.x >= off) ? sh[threadIdx.x - off] : 0;
        __syncthreads();
        sh[threadIdx.x] += t;
        __syncthreads();
    }
    if (gid <= NN) g_ptr[gid] = sh[threadIdx.x] - v;
    if (threadIdx.x == 511) g_bsums[blockIdx.x] = sh[511];
}

__global__ void k_scan2(int nb) {
    if (threadIdx.x == 0 && blockIdx.x == 0) {
        int acc = 0;
        for (int i = 0; i < nb; i++) { int t = g_bsums[i]; g_bsums[i] = acc; acc += t; }
    }
}

__global__ void k_scan3() {
    int gid = blockIdx.x * 512 + threadIdx.x;
    if (gid <= NN) {
        int p = g_ptr[gid] + g_bsums[blockIdx.x];
        g_ptr[gid] = p;
        if (gid < NN) g_fill[gid] = p;
    }
}

__global__ void k_scatter(const void* ei, int E) {
    int e = blockIdx.x * blockDim.x + threadIdx.x;
    if (e < E) {
        int s, d;
        load_edge(ei, E, e, s, d);
        float w = -(g_dinv[s] * g_dinv[d]);
        int pos = atomicAdd(&g_fill[d], 1);
        g_edge[pos] = make_int2(s, __float_as_int(w));
    }
}

// ------------------------- layer-1 sparse (F=3), MLP-4 unrolled -------------------------
__global__ void k_spmm3(const float* __restrict__ x, int xc, int yc, int subc) {
    int i = blockIdx.x * blockDim.x + threadIdx.x;
    if (i >= NN) return;
    const float* X = (xc == 0) ? x : (xc == 1) ? g_t1 : (xc == 2) ? g_t2 : g_t3;
    float*       Y = (yc == 1) ? g_t1 : (yc == 2) ? g_t2 : g_t3;
    int b = g_ptr[i], en = g_ptr[i + 1];
    float a0 = 0, a1 = 0, a2 = 0;
    int e = b;
    for (; e + 4 <= en; e += 4) {
        int2 e0 = __ldg(&g_edge[e]);
        int2 e1 = __ldg(&g_edge[e + 1]);
        int2 e2 = __ldg(&g_edge[e + 2]);
        int2 e3 = __ldg(&g_edge[e + 3]);
        float3 v0 = *(const float3*)(X + 3 * e0.x);
        float3 v1 = *(const float3*)(X + 3 * e1.x);
        float3 v2 = *(const float3*)(X + 3 * e2.x);
        float3 v3 = *(const float3*)(X + 3 * e3.x);
        float w0 = __int_as_float(e0.y), w1 = __int_as_float(e1.y);
        float w2 = __int_as_float(e2.y), w3 = __int_as_float(e3.y);
        a0 = fmaf(w0, v0.x, a0); a1 = fmaf(w0, v0.y, a1); a2 = fmaf(w0, v0.z, a2);
        a0 = fmaf(w1, v1.x, a0); a1 = fmaf(w1, v1.y, a1); a2 = fmaf(w1, v1.z, a2);
        a0 = fmaf(w2, v2.x, a0); a1 = fmaf(w2, v2.y, a1); a2 = fmaf(w2, v2.z, a2);
        a0 = fmaf(w3, v3.x, a0); a1 = fmaf(w3, v3.y, a1); a2 = fmaf(w3, v3.z, a2);
    }
    for (; e < en; e++) {
        int2 ed = __ldg(&g_edge[e]);
        float ww = __int_as_float(ed.y);
        const float* xr = X + 3 * ed.x;
        a0 = fmaf(ww, xr[0], a0);
        a1 = fmaf(ww, xr[1], a1);
        a2 = fmaf(ww, xr[2], a2);
    }
    float* y = Y + 3 * i;
    if (subc < 0) {
        y[0] = a0; y[1] = a1; y[2] = a2;
    } else {
        const float* S = (subc == 0) ? x : (subc == 1) ? g_t1 : (subc == 2) ? g_t2 : g_t3;
        y[0] = 2.0f * a0 - S[3 * i + 0];
        y[1] = 2.0f * a1 - S[3 * i + 1];
        y[2] = 2.0f * a2 - S[3 * i + 2];
    }
}

// ------------------------- F=128 SpMM: half-warp per node, MLP-4 unrolled -------------------------
// 16 lanes x uint4 (16B fp16) = full 256B row per gather. 2 nodes per warp.
__global__ void __launch_bounds__(256) k_spmm128h(int xseg, int yseg, int subseg) {
    int node = blockIdx.x * 16 + (threadIdx.x >> 4);
    if (node >= NN) return;
    int hl = threadIdx.x & 15;
    int b = g_ptr[node], en = g_ptr[node + 1];
    float acc[8] = {0, 0, 0, 0, 0, 0, 0, 0};
    const uint4* Xb = (const uint4*)g_Thalf;       // row = 64 uint4
    const uint32_t xo = xseg * 16 + hl;

    int e = b;
    for (; e + 4 <= en; e += 4) {
        int2 e0 = __ldg(&g_edge[e]);
        int2 e1 = __ldg(&g_edge[e + 1]);
        int2 e2 = __ldg(&g_edge[e + 2]);
        int2 e3 = __ldg(&g_edge[e + 3]);
        uint4 v0 = __ldg(&Xb[(size_t)e0.x * 64 + xo]);
        uint4 v1 = __ldg(&Xb[(size_t)e1.x * 64 + xo]);
        uint4 v2 = __ldg(&Xb[(size_t)e2.x * 64 + xo]);
        uint4 v3 = __ldg(&Xb[(size_t)e3.x * 64 + xo]);
        acc8(acc, v0, __int_as_float(e0.y));
        acc8(acc, v1, __int_as_float(e1.y));
        acc8(acc, v2, __int_as_float(e2.y));
        acc8(acc, v3, __int_as_float(e3.y));
    }
    for (; e < en; e++) {
        int2 ed = __ldg(&g_edge[e]);
        uint4 v = __ldg(&Xb[(size_t)ed.x * 64 + xo]);
        acc8(acc, v, __int_as_float(ed.y));
    }

    float* yrow = g_Tcat + (size_t)node * 512 + yseg * 128 + hl * 8;
    if (subseg >= 0) {
        const float* srow = g_Tcat + (size_t)node * 512 + subseg * 128 + hl * 8;
        float4 s0 = *(const float4*)srow;
        float4 s1 = *(const float4*)(srow + 4);
        acc[0] = 2.0f * acc[0] - s0.x;
        acc[1] = 2.0f * acc[1] - s0.y;
        acc[2] = 2.0f * acc[2] - s0.z;
        acc[3] = 2.0f * acc[3] - s0.w;
        acc[4] = 2.0f * acc[4] - s1.x;
        acc[5] = 2.0f * acc[5] - s1.y;
        acc[6] = 2.0f * acc[6] - s1.z;
        acc[7] = 2.0f * acc[7] - s1.w;
    }
    *(float4*)yrow = make_float4(acc[0], acc[1], acc[2], acc[3]);
    *(float4*)(yrow + 4) = make_float4(acc[4], acc[5], acc[6], acc[7]);
    if (yseg < 3) {
        uint4 o;
        o.x = packh2(acc[0], acc[1]);
        o.y = packh2(acc[2], acc[3]);
        o.z = packh2(acc[4], acc[5]);
        o.w = packh2(acc[6], acc[7]);
        *((uint4*)g_Thalf + (size_t)node * 64 + yseg * 16 + hl) = o;
    }
}

// ------------------------- layer-1 GEMM (12 x 128) -------------------------
__global__ void __launch_bounds__(256) k_gemm1(const float* __restrict__ x,
                                               const float* __restrict__ W1,
                                               const float* __restrict__ b1) {
    __shared__ float shW[12 * 128];
    __shared__ float shT[32 * 12];
    int tid = threadIdx.x;
    for (int i = tid; i < 1536; i += 256) shW[i] = W1[i];
    int r0 = blockIdx.x * 32;
    for (int i = tid; i < 384; i += 256) {
        int r = i / 12, j = i % 12;
        int k = j / 3, d = j % 3;
        int gr = r0 + r;
        float v = 0.0f;
        if (gr < NN) {
            const float* src = (k == 0) ? x : (k == 1) ? g_t1 : (k == 2) ? g_t2 : g_t3;
            v = src[gr * 3 + d];
        }
        shT[i] = v;
    }
    __syncthreads();
    int r = tid >> 3;
    int c0 = (tid & 7) * 16;
    int gr = r0 + r;
    if (gr < NN) {
        #pragma unroll
        for (int c = c0; c < c0 + 16; c++) {
            float acc = b1[c];
            #pragma unroll
            for (int j = 0; j < 12; j++) acc = fmaf(shT[r * 12 + j], shW[j * 128 + c], acc);
            g_H[(size_t)gr * 128 + c] = acc;
        }
    }
}

// ------------------------- weight prep -------------------------
__global__ void k_prepw(const float* __restrict__ W) {
    int i = blockIdx.x * 256 + threadIdx.x;
    if (i < 256 * 128) {
        int kp = i >> 7, n = i & 127;
        float x0 = W[(2 * kp) * 128 + n];
        float x1 = W[(2 * kp + 1) * 128 + n];
        uint32_t hi, lo;
        split2(x0, x1, hi, lo);
        g_Wbhi[i] = hi;
        g_Wblo[i] = lo;
    }
}

// ------------------------- bf16 split-precision mma.sync GEMM -------------------------
#define AST 20
#define BST 136
#define A_UINTS (128 * AST)
#define B_UINTS (16 * BST)
#define STAGE_UINTS (2 * A_UINTS + 2 * B_UINTS)
#define SMEM_GEMM (2 * STAGE_UINTS * 4)

__global__ void __launch_bounds__(256, 2) k_gemm_bf(const float* __restrict__ bias) {
    extern __shared__ uint32_t sm[];
    const int tid = threadIdx.x;
    const int lane = tid & 31;
    const int wid = tid >> 5;
    const int wm = wid & 3;
    const int wn = wid >> 2;
    const int lk = lane & 3;
    const int lr = lane >> 2;
    const int row0 = blockIdx.x * 128;
    const uint32_t sbase = smem_u32(sm);

    float acc[2][8][4];
    #pragma unroll
    for (int mt = 0; mt < 2; mt++)
        #pragma unroll
        for (int nt = 0; nt < 8; nt++)
            #pragma unroll
            for (int q = 0; q < 4; q++) acc[mt][nt][q] = 0.0f;

    float4 areg[4];

    {
        uint32_t bh_s = sbase + (2 * A_UINTS) * 4;
        uint32_t bl_s = bh_s + B_UINTS * 4;
        #pragma unroll
        for (int j = 0; j < 2; j++) {
            int q = tid * 2 + j;
            int kp = q >> 5, n4 = (q & 31) * 4;
            cp16(bh_s + (kp * BST + n4) * 4, &g_Wbhi[kp * 128 + n4]);
            cp16(bl_s + (kp * BST + n4) * 4, &g_Wblo[kp * 128 + n4]);
        }
        asm volatile("cp.async.commit_group;" ::: "memory");
        #pragma unroll
        for (int i = 0; i < 4; i++) {
            int idx = tid + (i << 8);
            int r = idx >> 3, kq = (idx & 7) << 2;
            int gr = row0 + r;
            areg[i] = (gr < NN) ? *(const float4*)&g_Tcat[(size_t)gr * 512 + kq]
                                : make_float4(0, 0, 0, 0);
        }
        uint32_t* Ah = sm;
        uint32_t* Al = sm + A_UINTS;
        #pragma unroll
        for (int i = 0; i < 4; i++) {
            int idx = tid + (i << 8);
            int r = idx >> 3, kq = (idx & 7) << 2;
            uint32_t h0, l0, h1, l1;
            split2(areg[i].x, areg[i].y, h0, l0);
            split2(areg[i].z, areg[i].w, h1, l1);
            uint32_t* d = Ah + r * AST + (kq >> 1);
            d[0] = h0; d[1] = h1;
            uint32_t* dl = Al + r * AST + (kq >> 1);
            dl[0] = l0; dl[1] = l1;
        }
        asm volatile("cp.async.wait_group 0;" ::: "memory");
        __syncthreads();
    }

    for (int c = 0; c < 16; c++) {
        int st = c & 1;
        int nst = st ^ 1;
        if (c < 15) {
            uint32_t bh_s = sbase + (nst * STAGE_UINTS + 2 * A_UINTS) * 4;
            uint32_t bl_s = bh_s + B_UINTS * 4;
            int kbase = (c + 1) * 16;
            #pragma unroll
            for (int j = 0; j < 2; j++) {
                int q = tid * 2 + j;
                int kp = q >> 5, n4 = (q & 31) * 4;
                cp16(bh_s + (kp * BST + n4) * 4, &g_Wbhi[(kbase + kp) * 128 + n4]);
                cp16(bl_s + (kp * BST + n4) * 4, &g_Wblo[(kbase + kp) * 128 + n4]);
            }
            asm volatile("cp.async.commit_group;" ::: "memory");
            int k0 = (c + 1) * 32;
            #pragma unroll
            for (int i = 0; i < 4; i++) {
                int idx = tid + (i << 8);
                int r = idx >> 3, kq = (idx & 7) << 2;
                int gr = row0 + r;
                areg[i] = (gr < NN) ? *(const float4*)&g_Tcat[(size_t)gr * 512 + k0 + kq]
                                    : make_float4(0, 0, 0, 0);
            }
        }

        {
            const uint32_t* Ah = sm + st * STAGE_UINTS;
            const uint32_t* Al = Ah + A_UINTS;
            const uint32_t* Bh = Al + A_UINTS;
            const uint32_t* Bl = Bh + B_UINTS;
            #pragma unroll
            for (int ks = 0; ks < 2; ks++) {
                int kpb = ks * 8;
                uint32_t ah[2][4], al[2][4];
                #pragma unroll
                for (int mt = 0; mt < 2; mt++) {
                    int r = wm * 32 + mt * 16 + lr;
                    const uint32_t* A0 = Ah + r * AST + kpb + lk;
                    ah[mt][0] = A0[0];
                    ah[mt][1] = A0[8 * AST];
                    ah[mt][2] = A0[4];
                    ah[mt][3] = A0[8 * AST + 4];
                    const uint32_t* A1 = Al + r * AST + kpb + lk;
                    al[mt][0] = A1[0];
                    al[mt][1] = A1[8 * AST];
                    al[mt][2] = A1[4];
                    al[mt][3] = A1[8 * AST + 4];
                }
                #pragma unroll
                for (int nt = 0; nt < 8; nt++) {
                    int col = wn * 64 + nt * 8 + lr;
                    const uint32_t* B0 = Bh + (kpb + lk) * BST + col;
                    uint32_t bh0 = B0[0], bh1 = B0[4 * BST];
                    const uint32_t* B1 = Bl + (kpb + lk) * BST + col;
                    uint32_t bl0 = B1[0], bl1 = B1[4 * BST];
                    #pragma unroll
                    for (int mt = 0; mt < 2; mt++) {
                        MMA16816(acc[mt][nt], ah[mt], bh0, bh1);
                        MMA16816(acc[mt][nt], ah[mt], bl0, bl1);
                        MMA16816(acc[mt][nt], al[mt], bh0, bh1);
                    }
                }
            }
        }

        if (c < 15) {
            uint32_t* Ah = sm + nst * STAGE_UINTS;
            uint32_t* Al = Ah + A_UINTS;
            #pragma unroll
            for (int i = 0; i < 4; i++) {
                int idx = tid + (i << 8);
                int r = idx >> 3, kq = (idx & 7) << 2;
                uint32_t h0, l0, h1, l1;
                split2(areg[i].x, areg[i].y, h0, l0);
                split2(areg[i].z, areg[i].w, h1, l1);
                uint32_t* d = Ah + r * AST + (kq >> 1);
                d[0] = h0; d[1] = h1;
                uint32_t* dl = Al + r * AST + (kq >> 1);
                dl[0] = l0; dl[1] = l1;
            }
            asm volatile("cp.async.wait_group 0;" ::: "memory");
        }
        __syncthreads();
    }

    #pragma unroll
    for (int mt = 0; mt < 2; mt++) {
        int r1 = row0 + wm * 32 + mt * 16 + lr;
        int r2 = r1 + 8;
        #pragma unroll
        for (int nt = 0; nt < 8; nt++) {
            int col = wn * 64 + nt * 8 + 2 * lk;
            float2 bs = *(const float2*)&bias[col];
            if (r1 < NN) {
                float2 o;
                o.x = acc[mt][nt][0] + bs.x;
                o.y = acc[mt][nt][1] + bs.y;
                *(float2*)&g_H[(size_t)r1 * 128 + col] = o;
            }
            if (r2 < NN) {
                float2 o;
                o.x = acc[mt][nt][2] + bs.x;
                o.y = acc[mt][nt][3] + bs.y;
                *(float2*)&g_H[(size_t)r2 * 128 + col] = o;
            }
        }
    }
}

// ------------------------- BN (two-pass deterministic) -------------------------
__device__ __forceinline__ float apply_act(float v, int act) {
    return act ? fmaxf(v, 0.0f) : (v >= 0.0f ? v : NEG * v);
}

__global__ void __launch_bounds__(128) k_colstat1(int act) {
    int c = threadIdx.x;
    float s = 0.0f, s2 = 0.0f;
    for (int r = blockIdx.x; r < NN; r += NSTAT) {
        float v = g_H[(size_t)r * 128 + c];
        v = apply_act(v, act);
        s += v;
        s2 = fmaf(v, v, s2);
    }
    g_part[blockIdx.x * 256 + c] = s;
    g_part[blockIdx.x * 256 + 128 + c] = s2;
}

__global__ void __launch_bounds__(128) k_colstat2(const float* __restrict__ gamma,
                                                  const float* __restrict__ beta) {
    int c = threadIdx.x;
    float s = 0.0f, s2 = 0.0f;
    for (int b = 0; b < NSTAT; b++) {
        s += g_part[b * 256 + c];
        s2 += g_part[b * 256 + 128 + c];
    }
    float mu = s / (float)NN;
    float var = s2 / (float)NN - mu * mu;
    float sc = gamma[c] * rsqrtf(var + BN_EPS);
    g_scale[c] = sc;
    g_shift[c] = beta[c] - mu * sc;
}

__global__ void __launch_bounds__(256) k_bnapply(int act) {
    int idx = blockIdx.x * blockDim.x + threadIdx.x;
    if (idx < NN * 64) {
        int p = idx & 63;
        int r = idx >> 6;
        int c = p * 2;
        float2 h = *(const float2*)&g_H[(size_t)r * 128 + c];
        float v0 = fmaf(apply_act(h.x, act), g_scale[c],     g_shift[c]);
        float v1 = fmaf(apply_act(h.y, act), g_scale[c + 1], g_shift[c + 1]);
        *(float2*)&g_Tcat[(size_t)r * 512 + c] = make_float2(v0, v1);
        g_Thalf[(size_t)r * 256 + p] = packh2(v0, v1);
    }
}

// ------------------------- final: L2 norm + head -------------------------
__global__ void __launch_bounds__(256) k_final(const float* __restrict__ Wrep,
                                               const float* __restrict__ brep,
                                               float* __restrict__ out) {
    __shared__ float shW[384];
    int tid = threadIdx.x;
    for (int i = tid; i < 384; i += 256) shW[i] = Wrep[i];
    __syncthreads();
    int node = blockIdx.x * 8 + (tid >> 5);
    int lane = tid & 31;
    if (node >= NN) return;
    float4 h = *(const float4*)&g_H[(size_t)node * 128 + lane * 4];
    float hv[4] = {h.x, h.y, h.z, h.w};
    float ss = 0.0f, p0 = 0.0f, p1 = 0.0f, p2 = 0.0f;
    #pragma unroll
    for (int q = 0; q < 4; q++) {
        int f = lane * 4 + q;
        ss = fmaf(hv[q], hv[q], ss);
        p0 = fmaf(hv[q], shW[f * 3 + 0], p0);
        p1 = fmaf(hv[q], shW[f * 3 + 1], p1);
        p2 = fmaf(hv[q], shW[f * 3 + 2], p2);
    }
    #pragma unroll
    for (int o = 16; o > 0; o >>= 1) {
        ss += __shfl_xor_sync(0xFFFFFFFFu, ss, o);
        p0 += __shfl_xor_sync(0xFFFFFFFFu, p0, o);
        p1 += __shfl_xor_sync(0xFFFFFFFFu, p1, o);
        p2 += __shfl_xor_sync(0xFFFFFFFFu, p2, o);
    }
    if (lane == 0) {
        float inv = 1.0f / fmaxf(sqrtf(ss), L2_EPS);
        out[node * 3 + 0] = fmaf(p0, inv, brep[0]);
        out[node * 3 + 1] = fmaf(p1, inv, brep[1]);
        out[node * 3 + 2] = fmaf(p2, inv, brep[2]);
    }
}

// ------------------------- host -------------------------
extern "C" void kernel_launch(void* const* d_in, const int* in_sizes, int n_in,
                              void* d_out, int out_size) {
    const float* x    = (const float*)d_in[0];
    const void*  ei   = d_in[1];
    const float* W1   = (const float*)d_in[2];
    const float* b1   = (const float*)d_in[3];
    const float* W2   = (const float*)d_in[4];
    const float* b2   = (const float*)d_in[5];
    const float* W3   = (const float*)d_in[6];
    const float* b3   = (const float*)d_in[7];
    const float* W4   = (const float*)d_in[8];
    const float* b4   = (const float*)d_in[9];
    const float* g1   = (const float*)d_in[10];
    const float* be1  = (const float*)d_in[11];
    const float* g2   = (const float*)d_in[12];
    const float* be2  = (const float*)d_in[13];
    const float* g3   = (const float*)d_in[14];
    const float* be3  = (const float*)d_in[15];
    const float* Wrep = (const float*)d_in[16];
    const float* brep = (const float*)d_in[17];
    float* out = (float*)d_out;

    int E = in_sizes[1] / 2;
    if (E > EE) E = EE;

    static int s_attr_done = 0;
    if (!s_attr_done) {
        cudaFuncSetAttribute(k_gemm_bf, cudaFuncAttributeMaxDynamicSharedMemorySize, SMEM_GEMM);
        s_attr_done = 1;
    }

    const int TB = 256;
    int gN = (NN + TB - 1) / TB;
    int gE = (E + TB - 1) / TB;
    int gHalf = (NN + 15) / 16;     // half-warp-per-node kernels, 16 nodes/block
    int gScan = (NN + 1 + 511) / 512;
    int gGemm = (NN + 127) / 128;
    int gBN = (NN * 64 + TB - 1) / TB;
    int gWarp = (NN + 7) / 8;

    // ---- graph structure ----
    k_detect<<<1, 32>>>((const int*)ei);
    k_zero<<<gN, TB>>>();
    k_count<<<gE, TB>>>(ei, E);
    k_dinv<<<gN, TB>>>();
    k_scan1<<<gScan, 512>>>();
    k_scan2<<<1, 1>>>(gScan);
    k_scan3<<<gScan, 512>>>();
    k_scatter<<<gE, TB>>>(ei, E);

    // ---- layer 1 (F=3) ----
    k_spmm3<<<gN, TB>>>(x, 0, 1, -1);
    k_spmm3<<<gN, TB>>>(x, 1, 2, 0);
    k_spmm3<<<gN, TB>>>(x, 2, 3, 1);
    k_gemm1<<<(NN + 31) / 32, 256>>>(x, W1, b1);
    k_colstat1<<<NSTAT, 128>>>(0);
    k_colstat2<<<1, 128>>>(g1, be1);
    k_bnapply<<<gBN, TB>>>(0);

    // ---- layer 2 ----
    k_spmm128h<<<gHalf, 256>>>(0, 1, -1);
    k_spmm128h<<<gHalf, 256>>>(1, 2, 0);
    k_spmm128h<<<gHalf, 256>>>(2, 3, 1);
    k_prepw<<<128, 256>>>(W2);
    k_gemm_bf<<<gGemm, 256, SMEM_GEMM>>>(b2);
    k_colstat1<<<NSTAT, 128>>>(0);
    k_colstat2<<<1, 128>>>(g2, be2);
    k_bnapply<<<gBN, TB>>>(0);

    // ---- layer 3 ----
    k_spmm128h<<<gHalf, 256>>>(0, 1, -1);
    k_spmm128h<<<gHalf, 256>>>(1, 2, 0);
    k_spmm128h<<<gHalf, 256>>>(2, 3, 1);
    k_prepw<<<128, 256>>>(W3);
    k_gemm_bf<<<gGemm, 256, SMEM_GEMM>>>(b3);
    k_colstat1<<<NSTAT, 128>>>(1);
    k_colstat2<<<1, 128>>>(g3, be3);
    k_bnapply<<<gBN, TB>>>(1);

    // ---- layer 4 ----
    k_spmm128h<<<gHalf, 256>>>(0, 1, -1);
    k_spmm128h<<<gHalf, 256>>>(1, 2, 0);
    k_spmm128h<<<gHalf, 256>>>(2, 3, 1);
    k_prepw<<<128, 256>>>(W4);
    k_gemm_bf<<<gGemm, 256, SMEM_GEMM>>>(b4);

    // ---- L2 norm + representation head ----
    k_final<<<gWarp, 256>>>(Wrep, brep, out);
}

// round 6
// speedup vs baseline: 1.8173x; 1.0910x over previous
#include <cuda_runtime.h>
#include <cuda_bf16.h>
#include <cuda_fp16.h>
#include <math.h>
#include <stdint.h>

#define NN 100000
#define NN_PAD 100096                   // multiple of 128; pad rows stay zero (.bss)
#define EE 1600000
#define HID 128
#define NEG 0.01f
#define BN_EPS 1e-5f
#define L2_EPS 1e-12f
#define NSTAT 512

// ------------------------- device scratch -------------------------
__device__ uint32_t g_Thalf[(size_t)NN_PAD * 256]; // [T0|T1|T2|T3] fp16 packed, 64 half2/seg
__device__ float g_H[(size_t)NN * 128];            // GEMM output (pre-activation)
__device__ float g_t1[NN * 3];
__device__ float g_t2[NN * 3];
__device__ float g_t3[NN * 3];
__device__ float g_deg[NN];
__device__ float g_dinv[NN];
__device__ int   g_indeg[NN];
__device__ int   g_ptr[NN + 1];
__device__ int   g_fill[NN];
__device__ int   g_bsums[256];
__device__ int2  g_edge[EE];                       // (src, w-as-int) CSR by dst
__device__ float g_part[NSTAT * 256];
__device__ float g_scale[128];
__device__ float g_shift[128];
__device__ uint32_t g_Wfhi[256 * 128];             // W fp16x2 along K: hi
__device__ uint32_t g_Wflo[256 * 128];             // residual lo
__device__ int   g_is64;

// ------------------------- helpers -------------------------
__device__ __forceinline__ uint32_t smem_u32(const void* p) {
    uint32_t a;
    asm("{ .reg .u64 t; cvta.to.shared.u64 t, %1; cvt.u32.u64 %0, t; }" : "=r"(a) : "l"(p));
    return a;
}

__device__ __forceinline__ uint32_t packh2(float a, float b) {
    __half2 h = __floats2half2_rn(a, b);
    return *reinterpret_cast<uint32_t*>(&h);
}

// fp16 split: x = hi + lo (lo captures rounding residual)
__device__ __forceinline__ void split2h(float x0, float x1, uint32_t& hi, uint32_t& lo) {
    __half h0 = __float2half_rn(x0);
    __half h1 = __float2half_rn(x1);
    float r0 = x0 - __half2float(h0);
    float r1 = x1 - __half2float(h1);
    __half2 H; H.x = h0; H.y = h1;
    hi = *reinterpret_cast<uint32_t*>(&H);
    lo = packh2(r0, r1);
}

#define MMAF16(c, a, b0, b1) \
    asm volatile("mma.sync.aligned.m16n8k16.row.col.f32.f16.f16.f32 " \
        "{%0,%1,%2,%3}, {%4,%5,%6,%7}, {%8,%9}, {%0,%1,%2,%3};" \
        : "+f"((c)[0]), "+f"((c)[1]), "+f"((c)[2]), "+f"((c)[3]) \
        : "r"((a)[0]), "r"((a)[1]), "r"((a)[2]), "r"((a)[3]), "r"(b0), "r"(b1))

__device__ __forceinline__ void cp16(uint32_t sdst, const void* gsrc) {
    asm volatile("cp.async.ca.shared.global [%0], [%1], 16;" :: "r"(sdst), "l"(gsrc) : "memory");
}

__device__ __forceinline__ void acc8(float* acc, uint4 v, float w) {
    float2 f0 = __half22float2(*reinterpret_cast<__half2*>(&v.x));
    float2 f1 = __half22float2(*reinterpret_cast<__half2*>(&v.y));
    float2 f2 = __half22float2(*reinterpret_cast<__half2*>(&v.z));
    float2 f3 = __half22float2(*reinterpret_cast<__half2*>(&v.w));
    acc[0] = fmaf(w, f0.x, acc[0]);
    acc[1] = fmaf(w, f0.y, acc[1]);
    acc[2] = fmaf(w, f1.x, acc[2]);
    acc[3] = fmaf(w, f1.y, acc[3]);
    acc[4] = fmaf(w, f2.x, acc[4]);
    acc[5] = fmaf(w, f2.y, acc[5]);
    acc[6] = fmaf(w, f3.x, acc[6]);
    acc[7] = fmaf(w, f3.y, acc[7]);
}

// ------------------------- edge helpers -------------------------
__device__ __forceinline__ void load_edge(const void* ei, int E, int e, int& s, int& d) {
    if (g_is64) {
        const long long* p = (const long long*)ei;
        s = (int)p[e];
        d = (int)p[(size_t)E + e];
    } else {
        const int* p = (const int*)ei;
        s = p[e];
        d = p[E + e];
    }
}

// ------------------------- setup kernels -------------------------
__global__ void k_detect(const int* ei32) {
    if (threadIdx.x == 0 && blockIdx.x == 0) {
        int is64 = 1;
        for (int i = 0; i < 32; i++) {
            if (ei32[2 * i + 1] != 0) { is64 = 0; break; }
        }
        g_is64 = is64;
    }
}

__global__ void k_zero() {
    int i = blockIdx.x * blockDim.x + threadIdx.x;
    if (i < NN) { g_deg[i] = 0.0f; g_indeg[i] = 0; }
}

__global__ void k_count(const void* ei, int E) {
    int e = blockIdx.x * blockDim.x + threadIdx.x;
    if (e < E) {
        int s, d;
        load_edge(ei, E, e, s, d);
        atomicAdd(&g_deg[s], 1.0f);
        atomicAdd(&g_indeg[d], 1);
    }
}

__global__ void k_dinv() {
    int i = blockIdx.x * blockDim.x + threadIdx.x;
    if (i < NN) {
        float dg = g_deg[i];
        g_dinv[i] = (dg > 0.0f) ? rsqrtf(fmaxf(dg, 1.0f)) : 0.0f;
    }
}

__global__ void k_scan1() {
    __shared__ int sh[512];
    int gid = blockIdx.x * 512 + threadIdx.x;
    int v = (gid < NN) ? g_indeg[gid] : 0;
    sh[threadIdx.x] = v;
    __syncthreads();
    for (int off = 1; off < 512; off <<= 1) {
        int t = (threadIdx.x >= off) ? sh[threadIdx.x - off] : 0;
        __syncthreads();
        sh[threadIdx.x] += t;
        __syncthreads();
    }
    if (gid <= NN) g_ptr[gid] = sh[threadIdx.x] - v;
    if (threadIdx.x == 511) g_bsums[blockIdx.x] = sh[511];
}

__global__ void k_scan2(int nb) {
    if (threadIdx.x == 0 && blockIdx.x == 0) {
        int acc = 0;
        for (int i = 0; i < nb; i++) { int t = g_bsums[i]; g_bsums[i] = acc; acc += t; }
    }
}

__global__ void k_scan3() {
    int gid = blockIdx.x * 512 + threadIdx.x;
    if (gid <= NN) {
        int p = g_ptr[gid] + g_bsums[blockIdx.x];
        g_ptr[gid] = p;
        if (gid < NN) g_fill[gid] = p;
    }
}

__global__ void k_scatter(const void* ei, int E) {
    int e = blockIdx.x * blockDim.x + threadIdx.x;
    if (e < E) {
        int s, d;
        load_edge(ei, E, e, s, d);
        float w = -(g_dinv[s] * g_dinv[d]);
        int pos = atomicAdd(&g_fill[d], 1);
        g_edge[pos] = make_int2(s, __float_as_int(w));
    }
}

// ------------------------- layer-1 sparse (F=3), MLP-4 unrolled -------------------------
__global__ void k_spmm3(const float* __restrict__ x, int xc, int yc, int subc) {
    int i = blockIdx.x * blockDim.x + threadIdx.x;
    if (i >= NN) return;
    const float* X = (xc == 0) ? x : (xc == 1) ? g_t1 : (xc == 2) ? g_t2 : g_t3;
    float*       Y = (yc == 1) ? g_t1 : (yc == 2) ? g_t2 : g_t3;
    int b = g_ptr[i], en = g_ptr[i + 1];
    float a0 = 0, a1 = 0, a2 = 0;
    int e = b;
    for (; e + 4 <= en; e += 4) {
        int2 e0 = __ldg(&g_edge[e]);
        int2 e1 = __ldg(&g_edge[e + 1]);
        int2 e2 = __ldg(&g_edge[e + 2]);
        int2 e3 = __ldg(&g_edge[e + 3]);
        float3 v0 = *(const float3*)(X + 3 * e0.x);
        float3 v1 = *(const float3*)(X + 3 * e1.x);
        float3 v2 = *(const float3*)(X + 3 * e2.x);
        float3 v3 = *(const float3*)(X + 3 * e3.x);
        float w0 = __int_as_float(e0.y), w1 = __int_as_float(e1.y);
        float w2 = __int_as_float(e2.y), w3 = __int_as_float(e3.y);
        a0 = fmaf(w0, v0.x, a0); a1 = fmaf(w0, v0.y, a1); a2 = fmaf(w0, v0.z, a2);
        a0 = fmaf(w1, v1.x, a0); a1 = fmaf(w1, v1.y, a1); a2 = fmaf(w1, v1.z, a2);
        a0 = fmaf(w2, v2.x, a0); a1 = fmaf(w2, v2.y, a1); a2 = fmaf(w2, v2.z, a2);
        a0 = fmaf(w3, v3.x, a0); a1 = fmaf(w3, v3.y, a1); a2 = fmaf(w3, v3.z, a2);
    }
    for (; e < en; e++) {
        int2 ed = __ldg(&g_edge[e]);
        float ww = __int_as_float(ed.y);
        const float* xr = X + 3 * ed.x;
        a0 = fmaf(ww, xr[0], a0);
        a1 = fmaf(ww, xr[1], a1);
        a2 = fmaf(ww, xr[2], a2);
    }
    float* y = Y + 3 * i;
    if (subc < 0) {
        y[0] = a0; y[1] = a1; y[2] = a2;
    } else {
        const float* S = (subc == 0) ? x : (subc == 1) ? g_t1 : (subc == 2) ? g_t2 : g_t3;
        y[0] = 2.0f * a0 - S[3 * i + 0];
        y[1] = 2.0f * a1 - S[3 * i + 1];
        y[2] = 2.0f * a2 - S[3 * i + 2];
    }
}

// ------------------------- F=128 SpMM: half-warp per node, fp16 in/out -------------------------
__global__ void __launch_bounds__(256) k_spmm128h(int xseg, int yseg, int subseg) {
    int node = blockIdx.x * 16 + (threadIdx.x >> 4);
    if (node >= NN) return;
    int hl = threadIdx.x & 15;
    int b = g_ptr[node], en = g_ptr[node + 1];
    float acc[8] = {0, 0, 0, 0, 0, 0, 0, 0};
    const uint4* Xb = (const uint4*)g_Thalf;       // row = 64 uint4
    const uint32_t xo = xseg * 16 + hl;

    int e = b;
    for (; e + 4 <= en; e += 4) {
        int2 e0 = __ldg(&g_edge[e]);
        int2 e1 = __ldg(&g_edge[e + 1]);
        int2 e2 = __ldg(&g_edge[e + 2]);
        int2 e3 = __ldg(&g_edge[e + 3]);
        uint4 v0 = __ldg(&Xb[(size_t)e0.x * 64 + xo]);
        uint4 v1 = __ldg(&Xb[(size_t)e1.x * 64 + xo]);
        uint4 v2 = __ldg(&Xb[(size_t)e2.x * 64 + xo]);
        uint4 v3 = __ldg(&Xb[(size_t)e3.x * 64 + xo]);
        acc8(acc, v0, __int_as_float(e0.y));
        acc8(acc, v1, __int_as_float(e1.y));
        acc8(acc, v2, __int_as_float(e2.y));
        acc8(acc, v3, __int_as_float(e3.y));
    }
    for (; e < en; e++) {
        int2 ed = __ldg(&g_edge[e]);
        uint4 v = __ldg(&Xb[(size_t)ed.x * 64 + xo]);
        acc8(acc, v, __int_as_float(ed.y));
    }

    if (subseg >= 0) {
        uint4 s = __ldg((const uint4*)g_Thalf + (size_t)node * 64 + subseg * 16 + hl);
        float2 s0 = __half22float2(*reinterpret_cast<__half2*>(&s.x));
        float2 s1 = __half22float2(*reinterpret_cast<__half2*>(&s.y));
        float2 s2 = __half22float2(*reinterpret_cast<__half2*>(&s.z));
        float2 s3 = __half22float2(*reinterpret_cast<__half2*>(&s.w));
        acc[0] = 2.0f * acc[0] - s0.x;
        acc[1] = 2.0f * acc[1] - s0.y;
        acc[2] = 2.0f * acc[2] - s1.x;
        acc[3] = 2.0f * acc[3] - s1.y;
        acc[4] = 2.0f * acc[4] - s2.x;
        acc[5] = 2.0f * acc[5] - s2.y;
        acc[6] = 2.0f * acc[6] - s3.x;
        acc[7] = 2.0f * acc[7] - s3.y;
    }
    uint4 o;
    o.x = packh2(acc[0], acc[1]);
    o.y = packh2(acc[2], acc[3]);
    o.z = packh2(acc[4], acc[5]);
    o.w = packh2(acc[6], acc[7]);
    *((uint4*)g_Thalf + (size_t)node * 64 + yseg * 16 + hl) = o;
}

// ------------------------- layer-1 GEMM (12 x 128) -------------------------
__global__ void __launch_bounds__(256) k_gemm1(const float* __restrict__ x,
                                               const float* __restrict__ W1,
                                               const float* __restrict__ b1) {
    __shared__ float shW[12 * 128];
    __shared__ float shT[32 * 12];
    int tid = threadIdx.x;
    for (int i = tid; i < 1536; i += 256) shW[i] = W1[i];
    int r0 = blockIdx.x * 32;
    for (int i = tid; i < 384; i += 256) {
        int r = i / 12, j = i % 12;
        int k = j / 3, d = j % 3;
        int gr = r0 + r;
        float v = 0.0f;
        if (gr < NN) {
            const float* src = (k == 0) ? x : (k == 1) ? g_t1 : (k == 2) ? g_t2 : g_t3;
            v = src[gr * 3 + d];
        }
        shT[i] = v;
    }
    __syncthreads();
    int r = tid >> 3;
    int c0 = (tid & 7) * 16;
    int gr = r0 + r;
    if (gr < NN) {
        #pragma unroll
        for (int c = c0; c < c0 + 16; c++) {
            float acc = b1[c];
            #pragma unroll
            for (int j = 0; j < 12; j++) acc = fmaf(shT[r * 12 + j], shW[j * 128 + c], acc);
            g_H[(size_t)gr * 128 + c] = acc;
        }
    }
}

// ------------------------- weight prep: fp16 hi/lo packed along K -------------------------
__global__ void k_prepw(const float* __restrict__ W) {
    int i = blockIdx.x * 256 + threadIdx.x;
    if (i < 256 * 128) {
        int kp = i >> 7, n = i & 127;
        float x0 = W[(2 * kp) * 128 + n];
        float x1 = W[(2 * kp + 1) * 128 + n];
        uint32_t hi, lo;
        split2h(x0, x1, hi, lo);
        g_Wfhi[i] = hi;
        g_Wflo[i] = lo;
    }
}

// ------------------------- fp16 2-term mma.sync GEMM: Thalf(N x 512) @ W(512 x 128) -------------------------
#define AST 20                          // uint stride of A smem row (16 data + 4 pad)
#define BST 136
#define A_UINTS (128 * AST)             // 2560
#define B_UINTS (16 * BST)              // 2176
#define STAGE_UINTS (A_UINTS + 2 * B_UINTS)   // 6912
#define SMEM_GEMM (2 * STAGE_UINTS * 4)       // 55296 B

__global__ void __launch_bounds__(256, 2) k_gemm_f16(const float* __restrict__ bias) {
    extern __shared__ uint32_t sm[];
    const int tid = threadIdx.x;
    const int lane = tid & 31;
    const int wid = tid >> 5;
    const int wm = wid & 3;
    const int wn = wid >> 2;
    const int lk = lane & 3;
    const int lr = lane >> 2;
    const int row0 = blockIdx.x * 128;
    const uint32_t sbase = smem_u32(sm);

    float acc[2][8][4];
    #pragma unroll
    for (int mt = 0; mt < 2; mt++)
        #pragma unroll
        for (int nt = 0; nt < 8; nt++)
            #pragma unroll
            for (int q = 0; q < 4; q++) acc[mt][nt][q] = 0.0f;

    // issue loads of chunk c into stage buffer
    auto issue = [&](int c, int stage) {
        uint32_t Ab  = sbase + stage * STAGE_UINTS * 4;
        uint32_t Bhb = Ab + A_UINTS * 4;
        uint32_t Blb = Bhb + B_UINTS * 4;
        int auoff = (c >> 2) * 64 + (c & 3) * 16;      // uint offset into Thalf row
        #pragma unroll
        for (int j = 0; j < 2; j++) {
            int q = tid * 2 + j;                        // 0..511
            int r = q >> 2, s4 = (q & 3) * 4;
            cp16(Ab + (r * AST + s4) * 4,
                 g_Thalf + (size_t)(row0 + r) * 256 + auoff + s4);
        }
        int kb = c * 16;
        #pragma unroll
        for (int j = 0; j < 2; j++) {
            int q = tid * 2 + j;                        // 0..511
            int kp = q >> 5, n4 = (q & 31) * 4;
            cp16(Bhb + (kp * BST + n4) * 4, &g_Wfhi[(kb + kp) * 128 + n4]);
            cp16(Blb + (kp * BST + n4) * 4, &g_Wflo[(kb + kp) * 128 + n4]);
        }
    };

    issue(0, 0);
    asm volatile("cp.async.commit_group;" ::: "memory");
    asm volatile("cp.async.wait_group 0;" ::: "memory");
    __syncthreads();

    for (int c = 0; c < 16; c++) {
        int st = c & 1;
        if (c < 15) {
            issue(c + 1, st ^ 1);
            asm volatile("cp.async.commit_group;" ::: "memory");
        }
        {
            const uint32_t* A  = sm + st * STAGE_UINTS;
            const uint32_t* Bh = A + A_UINTS;
            const uint32_t* Bl = Bh + B_UINTS;
            #pragma unroll
            for (int ks = 0; ks < 2; ks++) {
                int kpb = ks * 8;
                uint32_t a[2][4];
                #pragma unroll
                for (int mt = 0; mt < 2; mt++) {
                    int r = wm * 32 + mt * 16 + lr;
                    const uint32_t* A0 = A + r * AST + kpb + lk;
                    a[mt][0] = A0[0];
                    a[mt][1] = A0[8 * AST];
                    a[mt][2] = A0[4];
                    a[mt][3] = A0[8 * AST + 4];
                }
                #pragma unroll
                for (int nt = 0; nt < 8; nt++) {
                    int col = wn * 64 + nt * 8 + lr;
                    uint32_t bh0 = Bh[(kpb + lk) * BST + col];
                    uint32_t bh1 = Bh[(kpb + lk + 4) * BST + col];
                    uint32_t bl0 = Bl[(kpb + lk) * BST + col];
                    uint32_t bl1 = Bl[(kpb + lk + 4) * BST + col];
                    #pragma unroll
                    for (int mt = 0; mt < 2; mt++) {
                        MMAF16(acc[mt][nt], a[mt], bh0, bh1);
                        MMAF16(acc[mt][nt], a[mt], bl0, bl1);
                    }
                }
            }
        }
        if (c < 15)
            asm volatile("cp.async.wait_group 0;" ::: "memory");
        __syncthreads();
    }

    // ---- epilogue: bias + fp32 store ----
    #pragma unroll
    for (int mt = 0; mt < 2; mt++) {
        int r1 = row0 + wm * 32 + mt * 16 + lr;
        int r2 = r1 + 8;
        #pragma unroll
        for (int nt = 0; nt < 8; nt++) {
            int col = wn * 64 + nt * 8 + 2 * lk;
            float2 bs = *(const float2*)&bias[col];
            if (r1 < NN) {
                float2 o;
                o.x = acc[mt][nt][0] + bs.x;
                o.y = acc[mt][nt][1] + bs.y;
                *(float2*)&g_H[(size_t)r1 * 128 + col] = o;
            }
            if (r2 < NN) {
                float2 o;
                o.x = acc[mt][nt][2] + bs.x;
                o.y = acc[mt][nt][3] + bs.y;
                *(float2*)&g_H[(size_t)r2 * 128 + col] = o;
            }
        }
    }
}

// ------------------------- BN (two-pass deterministic) -------------------------
__device__ __forceinline__ float apply_act(float v, int act) {
    return act ? fmaxf(v, 0.0f) : (v >= 0.0f ? v : NEG * v);
}

__global__ void __launch_bounds__(128) k_colstat1(int act) {
    int c = threadIdx.x;
    float s = 0.0f, s2 = 0.0f;
    for (int r = blockIdx.x; r < NN; r += NSTAT) {
        float v = g_H[(size_t)r * 128 + c];
        v = apply_act(v, act);
        s += v;
        s2 = fmaf(v, v, s2);
    }
    g_part[blockIdx.x * 256 + c] = s;
    g_part[blockIdx.x * 256 + 128 + c] = s2;
}

__global__ void __launch_bounds__(128) k_colstat2(const float* __restrict__ gamma,
                                                  const float* __restrict__ beta) {
    int c = threadIdx.x;
    float s = 0.0f, s2 = 0.0f;
    for (int b = 0; b < NSTAT; b++) {
        s += g_part[b * 256 + c];
        s2 += g_part[b * 256 + 128 + c];
    }
    float mu = s / (float)NN;
    float var = s2 / (float)NN - mu * mu;
    float sc = gamma[c] * rsqrtf(var + BN_EPS);
    g_scale[c] = sc;
    g_shift[c] = beta[c] - mu * sc;
}

// writes BN output to Thalf seg0 (fp16) only
__global__ void __launch_bounds__(256) k_bnapply(int act) {
    int idx = blockIdx.x * blockDim.x + threadIdx.x;
    if (idx < NN * 64) {
        int p = idx & 63;
        int r = idx >> 6;
        int c = p * 2;
        float2 h = *(const float2*)&g_H[(size_t)r * 128 + c];
        float v0 = fmaf(apply_act(h.x, act), g_scale[c],     g_shift[c]);
        float v1 = fmaf(apply_act(h.y, act), g_scale[c + 1], g_shift[c + 1]);
        g_Thalf[(size_t)r * 256 + p] = packh2(v0, v1);
    }
}

// ------------------------- final: L2 norm + head -------------------------
__global__ void __launch_bounds__(256) k_final(const float* __restrict__ Wrep,
                                               const float* __restrict__ brep,
                                               float* __restrict__ out) {
    __shared__ float shW[384];
    int tid = threadIdx.x;
    for (int i = tid; i < 384; i += 256) shW[i] = Wrep[i];
    __syncthreads();
    int node = blockIdx.x * 8 + (tid >> 5);
    int lane = tid & 31;
    if (node >= NN) return;
    float4 h = *(const float4*)&g_H[(size_t)node * 128 + lane * 4];
    float hv[4] = {h.x, h.y, h.z, h.w};
    float ss = 0.0f, p0 = 0.0f, p1 = 0.0f, p2 = 0.0f;
    #pragma unroll
    for (int q = 0; q < 4; q++) {
        int f = lane * 4 + q;
        ss = fmaf(hv[q], hv[q], ss);
        p0 = fmaf(hv[q], shW[f * 3 + 0], p0);
        p1 = fmaf(hv[q], shW[f * 3 + 1], p1);
        p2 = fmaf(hv[q], shW[f * 3 + 2], p2);
    }
    #pragma unroll
    for (int o = 16; o > 0; o >>= 1) {
        ss += __shfl_xor_sync(0xFFFFFFFFu, ss, o);
        p0 += __shfl_xor_sync(0xFFFFFFFFu, p0, o);
        p1 += __shfl_xor_sync(0xFFFFFFFFu, p1, o);
        p2 += __shfl_xor_sync(0xFFFFFFFFu, p2, o);
    }
    if (lane == 0) {
        float inv = 1.0f / fmaxf(sqrtf(ss), L2_EPS);
        out[node * 3 + 0] = fmaf(p0, inv, brep[0]);
        out[node * 3 + 1] = fmaf(p1, inv, brep[1]);
        out[node * 3 + 2] = fmaf(p2, inv, brep[2]);
    }
}

// ------------------------- host -------------------------
extern "C" void kernel_launch(void* const* d_in, const int* in_sizes, int n_in,
                              void* d_out, int out_size) {
    const float* x    = (const float*)d_in[0];
    const void*  ei   = d_in[1];
    const float* W1   = (const float*)d_in[2];
    const float* b1   = (const float*)d_in[3];
    const float* W2   = (const float*)d_in[4];
    const float* b2   = (const float*)d_in[5];
    const float* W3   = (const float*)d_in[6];
    const float* b3   = (const float*)d_in[7];
    const float* W4   = (const float*)d_in[8];
    const float* b4   = (const float*)d_in[9];
    const float* g1   = (const float*)d_in[10];
    const float* be1  = (const float*)d_in[11];
    const float* g2   = (const float*)d_in[12];
    const float* be2  = (const float*)d_in[13];
    const float* g3   = (const float*)d_in[14];
    const float* be3  = (const float*)d_in[15];
    const float* Wrep = (const float*)d_in[16];
    const float* brep = (const float*)d_in[17];
    float* out = (float*)d_out;

    int E = in_sizes[1] / 2;
    if (E > EE) E = EE;

    static int s_attr_done = 0;
    if (!s_attr_done) {
        cudaFuncSetAttribute(k_gemm_f16, cudaFuncAttributeMaxDynamicSharedMemorySize, SMEM_GEMM);
        s_attr_done = 1;
    }

    const int TB = 256;
    int gN = (NN + TB - 1) / TB;
    int gE = (E + TB - 1) / TB;
    int gHalf = (NN + 15) / 16;
    int gScan = (NN + 1 + 511) / 512;
    int gGemm = NN_PAD / 128;
    int gBN = (NN * 64 + TB - 1) / TB;
    int gWarp = (NN + 7) / 8;

    // ---- graph structure ----
    k_detect<<<1, 32>>>((const int*)ei);
    k_zero<<<gN, TB>>>();
    k_count<<<gE, TB>>>(ei, E);
    k_dinv<<<gN, TB>>>();
    k_scan1<<<gScan, 512>>>();
    k_scan2<<<1, 1>>>(gScan);
    k_scan3<<<gScan, 512>>>();
    k_scatter<<<gE, TB>>>(ei, E);

    // ---- layer 1 (F=3) ----
    k_spmm3<<<gN, TB>>>(x, 0, 1, -1);
    k_spmm3<<<gN, TB>>>(x, 1, 2, 0);
    k_spmm3<<<gN, TB>>>(x, 2, 3, 1);
    k_gemm1<<<(NN + 31) / 32, 256>>>(x, W1, b1);
    k_colstat1<<<NSTAT, 128>>>(0);
    k_colstat2<<<1, 128>>>(g1, be1);
    k_bnapply<<<gBN, TB>>>(0);

    // ---- layer 2 ----
    k_spmm128h<<<gHalf, 256>>>(0, 1, -1);
    k_spmm128h<<<gHalf, 256>>>(1, 2, 0);
    k_spmm128h<<<gHalf, 256>>>(2, 3, 1);
    k_prepw<<<128, 256>>>(W2);
    k_gemm_f16<<<gGemm, 256, SMEM_GEMM>>>(b2);
    k_colstat1<<<NSTAT, 128>>>(0);
    k_colstat2<<<1, 128>>>(g2, be2);
    k_bnapply<<<gBN, TB>>>(0);

    // ---- layer 3 ----
    k_spmm128h<<<gHalf, 256>>>(0, 1, -1);
    k_spmm128h<<<gHalf, 256>>>(1, 2, 0);
    k_spmm128h<<<gHalf, 256>>>(2, 3, 1);
    k_prepw<<<128, 256>>>(W3);
    k_gemm_f16<<<gGemm, 256, SMEM_GEMM>>>(b3);
    k_colstat1<<<NSTAT, 128>>>(1);
    k_colstat2<<<1, 128>>>(g3, be3);
    k_bnapply<<<gBN, TB>>>(1);

    // ---- layer 4 ----
    k_spmm128h<<<gHalf, 256>>>(0, 1, -1);
    k_spmm128h<<<gHalf, 256>>>(1, 2, 0);
    k_spmm128h<<<gHalf, 256>>>(2, 3, 1);
    k_prepw<<<128, 256>>>(W4);
    k_gemm_f16<<<gGemm, 256, SMEM_GEMM>>>(b4);

    // ---- L2 norm + representation head ----
    k_final<<<gWarp, 256>>>(Wrep, brep, out);
}